// round 12
// baseline (speedup 1.0000x reference)
#include <cuda_runtime.h>
#include <cuda_fp16.h>
#include <cstdint>
#include <stdint.h>
#include <math.h>

// ---------------- problem constants ----------------
#define BB 2
#define TT 2048
#define CC 1024
#define HH 16
#define DD 64
#define EE 8
#define HDIM 1536
#define M0 (BB*TT)
#define MG 9216
#define EPSV 1e-6f

#define N4C (CC*CC/4)
#define N4E (EE*HDIM*CC/4)
#define OFF_OW (3*CC*CC)
#define OFF_W1 (4*CC*CC)
#define OFF_W2 (OFF_W1 + EE*HDIM*CC)
#define OFF_W3 (OFF_W2 + EE*HDIM*CC)
#define W16TOT (OFF_W3 + EE*HDIM*CC)

// ---------------- device scratch ----------------
__device__ __half g_h16 [M0*CC];
__device__ __half g_qkv16[M0*3*CC];
__device__ __half g_y16 [M0*CC];
__device__ __half g_hn16[M0*CC];
__device__ __half g_gb16[MG*HDIM];
__device__ __half g_w16all[W16TOT];
__device__ int    g_counts[EE];
__device__ int    g_cursor[EE];
__device__ int    g_poff[EE+1];
__device__ int    g_perm[MG];
__device__ float  g_gatew[MG];
__device__ int    g_idx2[M0*2];
__device__ float  g_wts2[M0*2];

// ---------------- PTX helpers ----------------
__device__ __forceinline__ unsigned s2u(const void* p) {
    unsigned a;
    asm("{ .reg .u64 t; cvta.to.shared.u64 t, %1; cvt.u32.u64 %0, t; }" : "=r"(a) : "l"(p));
    return a;
}
__device__ __forceinline__ void ldm_x4(unsigned& r0, unsigned& r1, unsigned& r2, unsigned& r3, unsigned a) {
    asm volatile("ldmatrix.sync.aligned.m8n8.x4.shared.b16 {%0,%1,%2,%3}, [%4];"
                 : "=r"(r0), "=r"(r1), "=r"(r2), "=r"(r3) : "r"(a));
}
__device__ __forceinline__ void ldm_x4t(unsigned& r0, unsigned& r1, unsigned& r2, unsigned& r3, unsigned a) {
    asm volatile("ldmatrix.sync.aligned.m8n8.x4.trans.shared.b16 {%0,%1,%2,%3}, [%4];"
                 : "=r"(r0), "=r"(r1), "=r"(r2), "=r"(r3) : "r"(a));
}
__device__ __forceinline__ void mma16816(float& d0, float& d1, float& d2, float& d3,
                                         unsigned a0, unsigned a1, unsigned a2, unsigned a3,
                                         unsigned b0, unsigned b1) {
    asm volatile("mma.sync.aligned.m16n8k16.row.col.f32.f16.f16.f32 "
                 "{%0,%1,%2,%3}, {%4,%5,%6,%7}, {%8,%9}, {%0,%1,%2,%3};"
                 : "+f"(d0), "+f"(d1), "+f"(d2), "+f"(d3)
                 : "r"(a0), "r"(a1), "r"(a2), "r"(a3), "r"(b0), "r"(b1));
}
__device__ __forceinline__ unsigned h2exp2u(__half2 x) {
    unsigned r;
    asm("ex2.approx.f16x2 %0, %1;" : "=r"(r) : "r"(*(unsigned*)&x));
    return r;
}
#define CPA16(dst, src) asm volatile("cp.async.cg.shared.global [%0], [%1], 16;" :: "r"(dst), "l"(src))

#define QSCALE (0.125f * 1.4426950408889634f)   // 1/sqrt(D) * log2(e)

// ---------------- fused weight conversion + MoE bookkeeping init ----------------
__global__ void convw_k(const float4* __restrict__ q, const float4* __restrict__ k,
                        const float4* __restrict__ v, const float4* __restrict__ o,
                        const float4* __restrict__ w1, const float4* __restrict__ w2,
                        const float4* __restrict__ w3, __half2* __restrict__ dst,
                        int* __restrict__ counts, int* __restrict__ perm,
                        float* __restrict__ gatew) {
    int i = blockIdx.x*blockDim.x + threadIdx.x;
    if (i < EE) counts[i] = 0;
    if (i < MG) { perm[i] = 0; gatew[i] = 0.f; }
    if (i >= 4*N4C + 3*N4E) return;
    const float4* s;
    long base;
    if (i < 4*N4C) {
        int seg = i / N4C, off = i - seg*N4C;
        s = (seg == 0 ? q : seg == 1 ? k : seg == 2 ? v : o) + off;
        base = (long)seg*N4C + off;
    } else {
        int j = i - 4*N4C;
        int seg = j / N4E, off = j - seg*N4E;
        s = (seg == 0 ? w1 : seg == 1 ? w2 : w3) + off;
        base = (long)4*N4C + (long)seg*N4E + off;
    }
    float4 val = *s;
    dst[base*2]   = __floats2half2_rn(val.x, val.y);
    dst[base*2+1] = __floats2half2_rn(val.z, val.w);
}

// ---------------- RMSNorm (fp16 out) ----------------
__global__ void rmsnorm_k(const float* __restrict__ x, const float* __restrict__ w,
                          __half* __restrict__ o16) {
    int row = blockIdx.x;
    const float* xr = x + (long)row*CC;
    __shared__ float red[256];
    float s = 0.f;
    for (int c = threadIdx.x; c < CC; c += 256) { float v = xr[c]; s += v*v; }
    red[threadIdx.x] = s; __syncthreads();
    for (int st = 128; st > 0; st >>= 1) {
        if (threadIdx.x < st) red[threadIdx.x] += red[threadIdx.x+st];
        __syncthreads();
    }
    float inv = rsqrtf(red[0]/(float)CC + EPSV);
    for (int c = threadIdx.x; c < CC; c += 256)
        o16[(long)row*CC + c] = __float2half(w[c]*xr[c]*inv);
}

// ---------------- fused ffn RMSNorm + router (per-row block) ----------------
__global__ void rmsnorm_router_k(const float* __restrict__ x, const float* __restrict__ w,
                                 __half* __restrict__ o16, const float* __restrict__ rw,
                                 int* __restrict__ idx2, float* __restrict__ wts2,
                                 int* __restrict__ counts) {
    int row = blockIdx.x;
    int tid = threadIdx.x, wid = tid >> 5, lane = tid & 31;
    const float* xr = x + (long)row*CC;
    __shared__ float sv[CC];
    __shared__ float red[256];
    __shared__ float lg[EE];
    float s = 0.f;
    #pragma unroll
    for (int j = 0; j < 4; j++) { float v = xr[tid + j*256]; s += v*v; }
    red[tid] = s; __syncthreads();
    for (int st = 128; st > 0; st >>= 1) {
        if (tid < st) red[tid] += red[tid+st];
        __syncthreads();
    }
    float inv = rsqrtf(red[0]/(float)CC + EPSV);
    #pragma unroll
    for (int j = 0; j < 4; j++) {
        int c = tid + j*256;
        float v = w[c]*xr[c]*inv;
        sv[c] = v;
        o16[(long)row*CC + c] = __float2half(v);
    }
    __syncthreads();
    {
        const float* rwe = rw + wid*CC;
        float acc = 0.f;
        #pragma unroll
        for (int i = 0; i < 32; i++) acc += sv[lane + i*32]*rwe[lane + i*32];
        #pragma unroll
        for (int o = 16; o > 0; o >>= 1) acc += __shfl_down_sync(0xffffffffu, acc, o);
        if (lane == 0) lg[wid] = acc;
    }
    __syncthreads();
    if (tid == 0) {
        int i0 = 0;
        #pragma unroll
        for (int e = 1; e < EE; e++) if (lg[e] > lg[i0]) i0 = e;
        int i1 = -1;
        #pragma unroll
        for (int e = 0; e < EE; e++) {
            if (e == i0) continue;
            if (i1 < 0 || lg[e] > lg[i1]) i1 = e;
        }
        float e1 = __expf(lg[i1] - lg[i0]);
        float sm = 1.f + e1;
        idx2[row*2]   = i0; idx2[row*2+1] = i1;
        wts2[row*2]   = 1.f/sm; wts2[row*2+1] = e1/sm;
        atomicAdd(&counts[i0], 1); atomicAdd(&counts[i1], 1);
    }
}

// ---------------- HMMA fp16 GEMM, 64x64 warp tiles, 3-stage; rope-fused fp16 epilogue ----------------
#define GBM 128
#define GBN 128
#define GBK 32
#define LDP 40
#define DSM_G (6*GBM*LDP*2)
__global__ __launch_bounds__(128)
void gemm16_k(const __half* __restrict__ A, const __half* __restrict__ Wb,
              float* __restrict__ Cout, __half* __restrict__ Cout16,
              int N, int K,
              const float* __restrict__ R,
              const int* __restrict__ perm,
              const int* __restrict__ poff,
              const float* __restrict__ rowscale,
              long wstride,
              const int* __restrict__ sperm,
              const float* __restrict__ ropeC,
              const float* __restrict__ ropeS) {
    extern __shared__ __half gsm[];
    __shared__ int rowsrc[GBM];

    int tid = threadIdx.x, wid = tid >> 5, lane = tid & 31;
    int tileN = blockIdx.x, tileM = blockIdx.y;
    int row0 = tileM*GBM;

    const __half* W = Wb;
    if (poff) {
        if (row0 >= poff[EE]) return;
        int e = 0;
        #pragma unroll
        for (int q2 = 1; q2 < EE; q2++) if (row0 >= poff[q2]) e = q2;
        W += (long)e * wstride;
    }
    if (tid < GBM) rowsrc[tid] = perm ? perm[row0 + tid] : (row0 + tid);
    __syncthreads();

    int warp_m = (wid & 1) * 64;
    int warp_n = (wid >> 1) * 64;

    unsigned sA[3], sB[3];
    #pragma unroll
    for (int i = 0; i < 3; i++) {
        sA[i] = s2u(gsm + i*GBM*LDP);
        sB[i] = s2u(gsm + (3 + i)*GBM*LDP);
    }

    auto load_stage = [&](int s) {
        int b = s % 3;
        long k0 = (long)s * GBK;
        #pragma unroll
        for (int c = 0; c < 4; c++) {
            int id = tid + c*128;
            int r = id >> 2, ch = id & 3;
            CPA16(sA[b] + (r*LDP + ch*8)*2, A + (long)rowsrc[r]*K + k0 + ch*8);
            CPA16(sB[b] + (r*LDP + ch*8)*2, W + (long)(tileN*GBN + r)*K + k0 + ch*8);
        }
        asm volatile("cp.async.commit_group;");
    };

    float acc[4][8][4] = {};
    int ns = K / GBK;
    load_stage(0);
    load_stage(1);

    for (int s = 0; s < ns; s++) {
        if (s + 1 < ns) asm volatile("cp.async.wait_group 1;");
        else            asm volatile("cp.async.wait_group 0;");
        __syncthreads();
        if (s + 2 < ns) load_stage(s + 2);
        int b = s % 3;
        #pragma unroll
        for (int kk = 0; kk < 2; kk++) {
            unsigned af[4][4], bf[4][4];
            #pragma unroll
            for (int mi = 0; mi < 4; mi++) {
                int r = warp_m + mi*16 + (lane & 15);
                int cH = kk*16 + ((lane >> 4) << 3);
                ldm_x4(af[mi][0], af[mi][1], af[mi][2], af[mi][3], sA[b] + (r*LDP + cH)*2);
            }
            #pragma unroll
            for (int pj = 0; pj < 4; pj++) {
                int n = warp_n + pj*16 + (lane & 7) + ((lane >> 4) << 3);
                int cH = kk*16 + (((lane >> 3) & 1) << 3);
                ldm_x4(bf[pj][0], bf[pj][1], bf[pj][2], bf[pj][3], sB[b] + (n*LDP + cH)*2);
            }
            #pragma unroll
            for (int mi = 0; mi < 4; mi++)
                #pragma unroll
                for (int nj = 0; nj < 8; nj++)
                    mma16816(acc[mi][nj][0], acc[mi][nj][1], acc[mi][nj][2], acc[mi][nj][3],
                             af[mi][0], af[mi][1], af[mi][2], af[mi][3],
                             bf[nj >> 1][(nj & 1)*2], bf[nj >> 1][(nj & 1)*2 + 1]);
        }
    }

    int lrow = lane >> 2;
    int lcol = (lane & 3) * 2;
    #pragma unroll
    for (int mi = 0; mi < 4; mi++) {
        #pragma unroll
        for (int half = 0; half < 2; half++) {
            int grow = row0 + warp_m + mi*16 + lrow + half*8;
            float sc = rowscale ? rowscale[grow] : 1.f;
            if (sperm) {
                if (sc != 0.f) {
                    int token = sperm[grow];
                    long obase = (long)token*N + tileN*GBN + warp_n;
                    #pragma unroll
                    for (int nj = 0; nj < 8; nj++) {
                        long off = obase + nj*8 + lcol;
                        atomicAdd(&Cout[off],     acc[mi][nj][half*2 + 0] * sc);
                        atomicAdd(&Cout[off + 1], acc[mi][nj][half*2 + 1] * sc);
                    }
                }
            } else if (ropeC) {
                int t = grow & (TT-1);
                long obase = (long)grow*N + tileN*GBN + warp_n;
                #pragma unroll
                for (int nj = 0; nj < 4; nj++) {
                    int colg = tileN*GBN + warp_n + nj*8 + lcol;
                    int seg = colg >> 10;            // 0=q,1=k,2=v
                    int d = colg & 63;               // 0..31 within head
                    float x1a = acc[mi][nj][half*2 + 0];
                    float x1b = acc[mi][nj][half*2 + 1];
                    float x2a = acc[mi][nj+4][half*2 + 0];
                    float x2b = acc[mi][nj+4][half*2 + 1];
                    if (seg < 2) {
                        const float* ct = ropeC + t*DD;
                        const float* st = ropeS + t*DD;
                        float c1a = ct[d],    c1b = ct[d+1];
                        float c2a = ct[d+32], c2b = ct[d+33];
                        float s1a = st[d],    s1b = st[d+1];
                        float s2a = st[d+32], s2b = st[d+33];
                        float o1a = x1a*c1a - x2a*s1a;
                        float o1b = x1b*c1b - x2b*s1b;
                        float o2a = x2a*c2a + x1a*s2a;
                        float o2b = x2b*c2b + x1b*s2b;
                        if (seg == 0) { o1a *= QSCALE; o1b *= QSCALE; o2a *= QSCALE; o2b *= QSCALE; }
                        x1a = o1a; x1b = o1b; x2a = o2a; x2b = o2b;
                    }
                    *(__half2*)(Cout16 + obase + nj*8 + lcol)        = __floats2half2_rn(x1a, x1b);
                    *(__half2*)(Cout16 + obase + (nj+4)*8 + lcol)    = __floats2half2_rn(x2a, x2b);
                }
            } else {
                long obase = (long)grow*N + tileN*GBN + warp_n;
                #pragma unroll
                for (int nj = 0; nj < 8; nj++) {
                    float vx = acc[mi][nj][half*2 + 0] * sc;
                    float vy = acc[mi][nj][half*2 + 1] * sc;
                    long off = obase + nj*8 + lcol;
                    if (Cout16) {
                        *(__half2*)(Cout16 + off) = __floats2half2_rn(vx, vy);
                    } else {
                        if (R) {
                            const float2 rv = *(const float2*)(R + off);
                            vx += rv.x; vy += rv.y;
                        }
                        float2 vv = { vx, vy };
                        *(float2*)(Cout + off) = vv;
                    }
                }
            }
        }
    }
}

// ---------------- fused MoE w1/w3 GEMM + silu*mul -> fp16, 3-stage ----------------
#define DSM_M (9*GBM*LDP*2)
__global__ __launch_bounds__(256)
void moe13_k(const __half* __restrict__ A, const __half* __restrict__ W1b,
             const __half* __restrict__ W3b, __half* __restrict__ G,
             const int* __restrict__ perm, const int* __restrict__ poff) {
    extern __shared__ __half sm[];
    __shared__ int rowsrc[GBM];

    int tid = threadIdx.x, wid = tid >> 5, lane = tid & 31;
    int tileN = blockIdx.x, tileM = blockIdx.y;
    int row0 = tileM*GBM;
    const int K = CC;

    if (row0 >= poff[EE]) return;
    int e = 0;
    #pragma unroll
    for (int q2 = 1; q2 < EE; q2++) if (row0 >= poff[q2]) e = q2;
    const __half* W1 = W1b + (long)e*HDIM*CC;
    const __half* W3 = W3b + (long)e*HDIM*CC;

    if (tid < GBM) rowsrc[tid] = perm[row0 + tid];
    __syncthreads();

    int warp_m = (wid >> 2) * 64;
    int warp_n = (wid & 3) * 32;

    unsigned sA[3], sB1[3], sB3[3];
    #pragma unroll
    for (int i = 0; i < 3; i++) {
        sA[i]  = s2u(sm + i*GBM*LDP);
        sB1[i] = s2u(sm + (3 + i)*GBM*LDP);
        sB3[i] = s2u(sm + (6 + i)*GBM*LDP);
    }

    auto load_stage = [&](int s) {
        int b = s % 3;
        long k0 = (long)s * GBK;
        #pragma unroll
        for (int c = 0; c < 2; c++) {
            int id = tid + c*256;
            int r = id >> 2, ch = id & 3;
            CPA16(sA[b]  + (r*LDP + ch*8)*2, A  + (long)rowsrc[r]*K + k0 + ch*8);
            CPA16(sB1[b] + (r*LDP + ch*8)*2, W1 + (long)(tileN*GBN + r)*K + k0 + ch*8);
            CPA16(sB3[b] + (r*LDP + ch*8)*2, W3 + (long)(tileN*GBN + r)*K + k0 + ch*8);
        }
        asm volatile("cp.async.commit_group;");
    };

    float a1[4][4][4] = {};
    float a3[4][4][4] = {};
    int ns = K / GBK;
    load_stage(0);
    load_stage(1);

    for (int s = 0; s < ns; s++) {
        if (s + 1 < ns) asm volatile("cp.async.wait_group 1;");
        else            asm volatile("cp.async.wait_group 0;");
        __syncthreads();
        if (s + 2 < ns) load_stage(s + 2);
        int b = s % 3;
        #pragma unroll
        for (int kk = 0; kk < 2; kk++) {
            unsigned af[4][4], b1f[2][4], b3f[2][4];
            #pragma unroll
            for (int mi = 0; mi < 4; mi++) {
                int r = warp_m + mi*16 + (lane & 15);
                int cH = kk*16 + ((lane >> 4) << 3);
                ldm_x4(af[mi][0], af[mi][1], af[mi][2], af[mi][3], sA[b] + (r*LDP + cH)*2);
            }
            #pragma unroll
            for (int pj = 0; pj < 2; pj++) {
                int n = warp_n + pj*16 + (lane & 7) + ((lane >> 4) << 3);
                int cH = kk*16 + (((lane >> 3) & 1) << 3);
                ldm_x4(b1f[pj][0], b1f[pj][1], b1f[pj][2], b1f[pj][3], sB1[b] + (n*LDP + cH)*2);
                ldm_x4(b3f[pj][0], b3f[pj][1], b3f[pj][2], b3f[pj][3], sB3[b] + (n*LDP + cH)*2);
            }
            #pragma unroll
            for (int mi = 0; mi < 4; mi++)
                #pragma unroll
                for (int nj = 0; nj < 4; nj++) {
                    mma16816(a1[mi][nj][0], a1[mi][nj][1], a1[mi][nj][2], a1[mi][nj][3],
                             af[mi][0], af[mi][1], af[mi][2], af[mi][3],
                             b1f[nj >> 1][(nj & 1)*2], b1f[nj >> 1][(nj & 1)*2 + 1]);
                    mma16816(a3[mi][nj][0], a3[mi][nj][1], a3[mi][nj][2], a3[mi][nj][3],
                             af[mi][0], af[mi][1], af[mi][2], af[mi][3],
                             b3f[nj >> 1][(nj & 1)*2], b3f[nj >> 1][(nj & 1)*2 + 1]);
                }
        }
    }

    int lrow = lane >> 2;
    int lcol = (lane & 3) * 2;
    #pragma unroll
    for (int mi = 0; mi < 4; mi++) {
        #pragma unroll
        for (int half = 0; half < 2; half++) {
            int grow = row0 + warp_m + mi*16 + lrow + half*8;
            long obase = (long)grow*HDIM + tileN*GBN + warp_n;
            #pragma unroll
            for (int nj = 0; nj < 4; nj++) {
                float u0 = a1[mi][nj][half*2 + 0];
                float u1 = a1[mi][nj][half*2 + 1];
                float w0 = a3[mi][nj][half*2 + 0];
                float w1 = a3[mi][nj][half*2 + 1];
                float g0 = u0 / (1.f + __expf(-u0)) * w0;
                float g1 = u1 / (1.f + __expf(-u1)) * w1;
                *(__half2*)(G + obase + nj*8 + lcol) = __floats2half2_rn(g0, g1);
            }
        }
    }
}

// ---------------- FlashAttention-2 HMMA causal attention, f16x2 MUFU softmax ----------------
#define ASTR 72
#define QKVS (3*CC)
#define FQT 128
#define DSM_F ((FQT*ASTR + 4*64*ASTR)*2)
__global__ __launch_bounds__(256)
void fattn_k(const __half* __restrict__ qkv, __half* __restrict__ y) {
    extern __shared__ __half fsm[];
    int qb = (int)gridDim.x - 1 - (int)blockIdx.x;
    int h = blockIdx.y, b = blockIdx.z;
    int tid = threadIdx.x, wid = tid >> 5, lane = tid & 31;

    unsigned uQ = s2u(fsm);
    unsigned uK[2] = { s2u(fsm + FQT*ASTR),              s2u(fsm + FQT*ASTR + 64*ASTR) };
    unsigned uV[2] = { s2u(fsm + FQT*ASTR + 2*64*ASTR),  s2u(fsm + FQT*ASTR + 3*64*ASTR) };

    long qbase = (long)(b*TT + qb*FQT)*QKVS + h*DD;
    #pragma unroll
    for (int c = 0; c < 4; c++) {
        int id = tid + c*256;
        int r = id >> 3, ch = id & 7;
        CPA16(uQ + (r*ASTR + ch*8)*2, qkv + qbase + (long)r*QKVS + ch*8);
    }
    asm volatile("cp.async.commit_group;");

    auto load_kv = [&](int s) {
        int bb = s & 1;
        long kvb = (long)(b*TT + s*64)*QKVS + h*DD + CC;
        #pragma unroll
        for (int c = 0; c < 2; c++) {
            int id = tid + c*256;
            int r = id >> 3, ch = id & 7;
            CPA16(uK[bb] + (r*ASTR + ch*8)*2, qkv + kvb + (long)r*QKVS + ch*8);
            CPA16(uV[bb] + (r*ASTR + ch*8)*2, qkv + kvb + CC + (long)r*QKVS + ch*8);
        }
        asm volatile("cp.async.commit_group;");
    };

    load_kv(0);
    asm volatile("cp.async.wait_group 0;");
    __syncthreads();

    unsigned qa[4][4];
    #pragma unroll
    for (int kk = 0; kk < 4; kk++) {
        int r = wid*16 + (lane & 15);
        int cH = kk*16 + ((lane >> 4) << 3);
        ldm_x4(qa[kk][0], qa[kk][1], qa[kk][2], qa[kk][3], uQ + (r*ASTR + cH)*2);
    }

    float m0 = -1e30f, m1 = -1e30f, l0 = 0.f, l1 = 0.f;
    float oa[8][4] = {};
    int nkt = 2*qb + 2;

    for (int kt = 0; kt < nkt; kt++) {
        if (kt + 1 < nkt) { load_kv(kt + 1); asm volatile("cp.async.wait_group 1;"); }
        else              { asm volatile("cp.async.wait_group 0;"); }
        __syncthreads();
        int bb = kt & 1;

        float sc[8][4] = {};
        #pragma unroll
        for (int kk = 0; kk < 4; kk++) {
            unsigned bf[4][4];
            #pragma unroll
            for (int pj = 0; pj < 4; pj++) {
                int n = pj*16 + (lane & 7) + ((lane >> 4) << 3);
                int cH = kk*16 + (((lane >> 3) & 1) << 3);
                ldm_x4(bf[pj][0], bf[pj][1], bf[pj][2], bf[pj][3], uK[bb] + (n*ASTR + cH)*2);
            }
            #pragma unroll
            for (int nj = 0; nj < 8; nj++)
                mma16816(sc[nj][0], sc[nj][1], sc[nj][2], sc[nj][3],
                         qa[kk][0], qa[kk][1], qa[kk][2], qa[kk][3],
                         bf[nj >> 1][(nj & 1)*2], bf[nj >> 1][(nj & 1)*2 + 1]);
        }

        if (kt >= 2*qb) {
            int rg = qb*FQT + wid*16 + (lane >> 2);
            #pragma unroll
            for (int nj = 0; nj < 8; nj++) {
                int cg = kt*64 + nj*8 + (lane & 3)*2;
                if (cg     > rg)   sc[nj][0] = -1e30f;
                if (cg + 1 > rg)   sc[nj][1] = -1e30f;
                if (cg     > rg+8) sc[nj][2] = -1e30f;
                if (cg + 1 > rg+8) sc[nj][3] = -1e30f;
            }
        }

        float rm0 = -1e30f, rm1 = -1e30f;
        #pragma unroll
        for (int nj = 0; nj < 8; nj++) {
            rm0 = fmaxf(rm0, fmaxf(sc[nj][0], sc[nj][1]));
            rm1 = fmaxf(rm1, fmaxf(sc[nj][2], sc[nj][3]));
        }
        rm0 = fmaxf(rm0, __shfl_xor_sync(0xffffffffu, rm0, 1));
        rm0 = fmaxf(rm0, __shfl_xor_sync(0xffffffffu, rm0, 2));
        rm1 = fmaxf(rm1, __shfl_xor_sync(0xffffffffu, rm1, 1));
        rm1 = fmaxf(rm1, __shfl_xor_sync(0xffffffffu, rm1, 2));
        float mn0 = fmaxf(m0, rm0), mn1 = fmaxf(m1, rm1);
        float corr0 = exp2f(m0 - mn0), corr1 = exp2f(m1 - mn1);
        m0 = mn0; m1 = mn1;

        // P = 2^(S-m) computed directly in fp16x2 on MUFU (results feed fp16 MMA anyway)
        unsigned pa[4][4];
        float ps0 = 0.f, ps1 = 0.f;
        #pragma unroll
        for (int j = 0; j < 4; j++) {
            __half2 d0 = __floats2half2_rn(sc[2*j][0]   - m0, sc[2*j][1]   - m0);
            __half2 d1 = __floats2half2_rn(sc[2*j][2]   - m1, sc[2*j][3]   - m1);
            __half2 d2 = __floats2half2_rn(sc[2*j+1][0] - m0, sc[2*j+1][1] - m0);
            __half2 d3 = __floats2half2_rn(sc[2*j+1][2] - m1, sc[2*j+1][3] - m1);
            unsigned e0 = h2exp2u(d0), e1 = h2exp2u(d1), e2 = h2exp2u(d2), e3 = h2exp2u(d3);
            pa[j][0] = e0; pa[j][1] = e1; pa[j][2] = e2; pa[j][3] = e3;
            float2 f0 = __half22float2(*(__half2*)&e0);
            float2 f1 = __half22float2(*(__half2*)&e1);
            float2 f2 = __half22float2(*(__half2*)&e2);
            float2 f3 = __half22float2(*(__half2*)&e3);
            ps0 += f0.x + f0.y + f2.x + f2.y;
            ps1 += f1.x + f1.y + f3.x + f3.y;
        }
        ps0 += __shfl_xor_sync(0xffffffffu, ps0, 1);
        ps0 += __shfl_xor_sync(0xffffffffu, ps0, 2);
        ps1 += __shfl_xor_sync(0xffffffffu, ps1, 1);
        ps1 += __shfl_xor_sync(0xffffffffu, ps1, 2);
        l0 = l0*corr0 + ps0;
        l1 = l1*corr1 + ps1;

        #pragma unroll
        for (int nj = 0; nj < 8; nj++) {
            oa[nj][0] *= corr0; oa[nj][1] *= corr0;
            oa[nj][2] *= corr1; oa[nj][3] *= corr1;
        }

        #pragma unroll
        for (int j = 0; j < 4; j++) {
            unsigned vf[4][4];
            #pragma unroll
            for (int pd = 0; pd < 4; pd++) {
                int r = j*16 + (lane & 15);
                int cH = pd*16 + ((lane >> 4) << 3);
                ldm_x4t(vf[pd][0], vf[pd][1], vf[pd][2], vf[pd][3], uV[bb] + (r*ASTR + cH)*2);
            }
            #pragma unroll
            for (int dn = 0; dn < 8; dn++)
                mma16816(oa[dn][0], oa[dn][1], oa[dn][2], oa[dn][3],
                         pa[j][0], pa[j][1], pa[j][2], pa[j][3],
                         vf[dn >> 1][(dn & 1)*2], vf[dn >> 1][(dn & 1)*2 + 1]);
        }
        __syncthreads();
    }

    float il0 = 1.f/l0, il1 = 1.f/l1;
    int r0 = qb*FQT + wid*16 + (lane >> 2);
    #pragma unroll
    for (int dn = 0; dn < 8; dn++) {
        int col = dn*8 + (lane & 3)*2;
        long o0 = ((long)(b*TT + r0)*HH + h)*DD + col;
        long o1 = ((long)(b*TT + r0 + 8)*HH + h)*DD + col;
        *(__half2*)(y + o0) = __floats2half2_rn(oa[dn][0]*il0, oa[dn][1]*il0);
        *(__half2*)(y + o1) = __floats2half2_rn(oa[dn][2]*il1, oa[dn][3]*il1);
    }
}

__global__ void offsets_k(const int* counts, int* poff, int* cursor) {
    if (threadIdx.x == 0 && blockIdx.x == 0) {
        int o = 0;
        for (int e = 0; e < EE; e++) {
            poff[e] = o; cursor[e] = 0;
            o += ((counts[e] + 127)/128)*128;
        }
        poff[EE] = o;
    }
}

__global__ void scatter_k(const int* __restrict__ idx2, const float* __restrict__ wts2,
                          int* __restrict__ cursor, const int* __restrict__ poff,
                          int* __restrict__ perm, float* __restrict__ gatew) {
    int t = blockIdx.x*blockDim.x + threadIdx.x;
    if (t >= M0) return;
    for (int kk = 0; kk < 2; kk++) {
        int e = idx2[t*2 + kk];
        int pos = atomicAdd(&cursor[e], 1);
        int r = poff[e] + pos;
        perm[r] = t; gatew[r] = wts2[t*2 + kk];
    }
}

// ---------------- launch ----------------
static void* sym(const void* s) { void* p = nullptr; cudaGetSymbolAddress(&p, s); return p; }

extern "C" void kernel_launch(void* const* d_in, const int* in_sizes, int n_in,
                              void* d_out, int out_size) {
    const float* x    = (const float*)d_in[0];
    const float* rc   = (const float*)d_in[1];
    const float* rs   = (const float*)d_in[2];
    const float* anw  = (const float*)d_in[3];
    const float* qw   = (const float*)d_in[4];
    const float* kw   = (const float*)d_in[5];
    const float* vw   = (const float*)d_in[6];
    const float* ow   = (const float*)d_in[7];
    const float* fnw  = (const float*)d_in[8];
    const float* rw   = (const float*)d_in[9];
    const float* w1   = (const float*)d_in[10];
    const float* w2   = (const float*)d_in[11];
    const float* w3   = (const float*)d_in[12];
    float* out = (float*)d_out;

    __half* h16   = (__half*)sym(g_h16);
    __half* qkv16 = (__half*)sym(g_qkv16);
    __half* y16   = (__half*)sym(g_y16);
    __half* hn16  = (__half*)sym(g_hn16);
    __half* gb16  = (__half*)sym(g_gb16);
    __half* w16   = (__half*)sym(g_w16all);
    __half* wqkv16= w16;
    __half* ow16  = w16 + OFF_OW;
    __half* w116  = w16 + OFF_W1;
    __half* w216  = w16 + OFF_W2;
    __half* w316  = w16 + OFF_W3;
    int*   counts = (int*)sym(g_counts);
    int*   cursor = (int*)sym(g_cursor);
    int*   poff   = (int*)sym(g_poff);
    int*   perm   = (int*)sym(g_perm);
    float* gatew  = (float*)sym(g_gatew);
    int*   idx2   = (int*)sym(g_idx2);
    float* wts2   = (float*)sym(g_wts2);

    cudaFuncSetAttribute(gemm16_k, cudaFuncAttributeMaxDynamicSharedMemorySize, DSM_G);
    cudaFuncSetAttribute(moe13_k, cudaFuncAttributeMaxDynamicSharedMemorySize, DSM_M);
    cudaFuncSetAttribute(fattn_k, cudaFuncAttributeMaxDynamicSharedMemorySize, DSM_F);

    // 0) fused weight conversion + MoE bookkeeping init
    int ncv = 4*N4C + 3*N4E;
    convw_k<<<(ncv + 255)/256, 256>>>((const float4*)qw, (const float4*)kw, (const float4*)vw,
                                      (const float4*)ow, (const float4*)w1, (const float4*)w2,
                                      (const float4*)w3, (__half2*)w16, counts, perm, gatew);
    // 1) attn rmsnorm (fp16 out)
    rmsnorm_k<<<M0, 256>>>(x, anw, h16);
    // 2) fused QKV projection with rope epilogue (fp16 out, q in log2 domain)
    gemm16_k<<<dim3(3*CC/GBN, M0/GBM), 128, DSM_G>>>(h16, wqkv16, nullptr, qkv16, 3*CC, CC,
                                                     nullptr, nullptr, nullptr, nullptr, 0, nullptr, rc, rs);
    // 3) causal flash attention (f16x2 MUFU softmax)
    fattn_k<<<dim3(TT/FQT, HH, BB), 256, DSM_F>>>(qkv16, y16);
    // 4) output projection + residual -> out
    gemm16_k<<<dim3(CC/GBN, M0/GBM), 128, DSM_G>>>(y16, ow16, out, nullptr, CC, CC,
                                                   x, nullptr, nullptr, nullptr, 0, nullptr, nullptr, nullptr);
    // 5) fused ffn rmsnorm + router
    rmsnorm_router_k<<<M0, 256>>>(out, fnw, hn16, rw, idx2, wts2, counts);
    // 6) gather bookkeeping
    offsets_k<<<1, 32>>>(counts, poff, cursor);
    scatter_k<<<(M0 + 255)/256, 256>>>(idx2, wts2, cursor, poff, perm, gatew);
    // 7) fused expert up-projection + silu*mul
    moe13_k<<<dim3(HDIM/GBN, MG/GBM), 256, DSM_M>>>(hn16, w116, w316, gb16, perm, poff);
    //    down-projection: gate-scaled atomic scatter into out
    gemm16_k<<<dim3(CC/GBN, MG/GBM), 128, DSM_G>>>(gb16, w216, out, nullptr, CC, HDIM,
                                                   nullptr, nullptr, poff, gatew, (long)CC*HDIM, perm, nullptr, nullptr);
}

// round 14
// speedup vs baseline: 1.0114x; 1.0114x over previous
#include <cuda_runtime.h>
#include <cuda_fp16.h>
#include <cstdint>
#include <stdint.h>
#include <math.h>

// ---------------- problem constants ----------------
#define BB 2
#define TT 2048
#define CC 1024
#define HH 16
#define DD 64
#define EE 8
#define HDIM 1536
#define M0 (BB*TT)
#define MG 9216
#define EPSV 1e-6f

#define N4C (CC*CC/4)
#define N4E (EE*HDIM*CC/4)
#define OFF_OW (3*CC*CC)
#define OFF_W1 (4*CC*CC)
#define OFF_W2 (OFF_W1 + EE*HDIM*CC)
#define OFF_W3 (OFF_W2 + EE*HDIM*CC)
#define W16TOT (OFF_W3 + EE*HDIM*CC)

// ---------------- device scratch ----------------
__device__ __half g_h16 [M0*CC];
__device__ __half g_qkv16[M0*3*CC];
__device__ __half g_y16 [M0*CC];
__device__ __half g_hn16[M0*CC];
__device__ __half g_gb16[MG*HDIM];
__device__ __half g_w16all[W16TOT];
__device__ int    g_counts[EE];
__device__ int    g_cursor[EE];
__device__ int    g_poff[EE+1];
__device__ int    g_perm[MG];
__device__ float  g_gatew[MG];
__device__ int    g_idx2[M0*2];
__device__ float  g_wts2[M0*2];

// ---------------- PTX helpers ----------------
__device__ __forceinline__ unsigned s2u(const void* p) {
    unsigned a;
    asm("{ .reg .u64 t; cvta.to.shared.u64 t, %1; cvt.u32.u64 %0, t; }" : "=r"(a) : "l"(p));
    return a;
}
__device__ __forceinline__ void ldm_x4(unsigned& r0, unsigned& r1, unsigned& r2, unsigned& r3, unsigned a) {
    asm volatile("ldmatrix.sync.aligned.m8n8.x4.shared.b16 {%0,%1,%2,%3}, [%4];"
                 : "=r"(r0), "=r"(r1), "=r"(r2), "=r"(r3) : "r"(a));
}
__device__ __forceinline__ void ldm_x4t(unsigned& r0, unsigned& r1, unsigned& r2, unsigned& r3, unsigned a) {
    asm volatile("ldmatrix.sync.aligned.m8n8.x4.trans.shared.b16 {%0,%1,%2,%3}, [%4];"
                 : "=r"(r0), "=r"(r1), "=r"(r2), "=r"(r3) : "r"(a));
}
__device__ __forceinline__ void mma16816(float& d0, float& d1, float& d2, float& d3,
                                         unsigned a0, unsigned a1, unsigned a2, unsigned a3,
                                         unsigned b0, unsigned b1) {
    asm volatile("mma.sync.aligned.m16n8k16.row.col.f32.f16.f16.f32 "
                 "{%0,%1,%2,%3}, {%4,%5,%6,%7}, {%8,%9}, {%0,%1,%2,%3};"
                 : "+f"(d0), "+f"(d1), "+f"(d2), "+f"(d3)
                 : "r"(a0), "r"(a1), "r"(a2), "r"(a3), "r"(b0), "r"(b1));
}
#define CPA16(dst, src) asm volatile("cp.async.cg.shared.global [%0], [%1], 16;" :: "r"(dst), "l"(src))

#define QSCALE (0.125f * 1.4426950408889634f)   // 1/sqrt(D) * log2(e)

// ---------------- fused weight conversion + MoE bookkeeping init ----------------
__global__ void convw_k(const float4* __restrict__ q, const float4* __restrict__ k,
                        const float4* __restrict__ v, const float4* __restrict__ o,
                        const float4* __restrict__ w1, const float4* __restrict__ w2,
                        const float4* __restrict__ w3, __half2* __restrict__ dst,
                        int* __restrict__ counts, int* __restrict__ cursor,
                        int* __restrict__ perm, float* __restrict__ gatew) {
    int i = blockIdx.x*blockDim.x + threadIdx.x;
    if (i < EE) { counts[i] = 0; cursor[i] = 0; }
    if (i < MG) { perm[i] = 0; gatew[i] = 0.f; }
    if (i >= 4*N4C + 3*N4E) return;
    const float4* s;
    long base;
    if (i < 4*N4C) {
        int seg = i / N4C, off = i - seg*N4C;
        s = (seg == 0 ? q : seg == 1 ? k : seg == 2 ? v : o) + off;
        base = (long)seg*N4C + off;
    } else {
        int j = i - 4*N4C;
        int seg = j / N4E, off = j - seg*N4E;
        s = (seg == 0 ? w1 : seg == 1 ? w2 : w3) + off;
        base = (long)4*N4C + (long)seg*N4E + off;
    }
    float4 val = *s;
    dst[base*2]   = __floats2half2_rn(val.x, val.y);
    dst[base*2+1] = __floats2half2_rn(val.z, val.w);
}

// ---------------- RMSNorm (fp16 out) ----------------
__global__ void rmsnorm_k(const float* __restrict__ x, const float* __restrict__ w,
                          __half* __restrict__ o16) {
    int row = blockIdx.x;
    const float* xr = x + (long)row*CC;
    __shared__ float red[256];
    float s = 0.f;
    for (int c = threadIdx.x; c < CC; c += 256) { float v = xr[c]; s += v*v; }
    red[threadIdx.x] = s; __syncthreads();
    for (int st = 128; st > 0; st >>= 1) {
        if (threadIdx.x < st) red[threadIdx.x] += red[threadIdx.x+st];
        __syncthreads();
    }
    float inv = rsqrtf(red[0]/(float)CC + EPSV);
    for (int c = threadIdx.x; c < CC; c += 256)
        o16[(long)row*CC + c] = __float2half(w[c]*xr[c]*inv);
}

// ---------------- fused ffn RMSNorm + router (per-row block) ----------------
__global__ void rmsnorm_router_k(const float* __restrict__ x, const float* __restrict__ w,
                                 __half* __restrict__ o16, const float* __restrict__ rw,
                                 int* __restrict__ idx2, float* __restrict__ wts2,
                                 int* __restrict__ counts) {
    int row = blockIdx.x;
    int tid = threadIdx.x, wid = tid >> 5, lane = tid & 31;
    const float* xr = x + (long)row*CC;
    __shared__ float sv[CC];
    __shared__ float red[256];
    __shared__ float lg[EE];
    float s = 0.f;
    #pragma unroll
    for (int j = 0; j < 4; j++) { float v = xr[tid + j*256]; s += v*v; }
    red[tid] = s; __syncthreads();
    for (int st = 128; st > 0; st >>= 1) {
        if (tid < st) red[tid] += red[tid+st];
        __syncthreads();
    }
    float inv = rsqrtf(red[0]/(float)CC + EPSV);
    #pragma unroll
    for (int j = 0; j < 4; j++) {
        int c = tid + j*256;
        float v = w[c]*xr[c]*inv;
        sv[c] = v;
        o16[(long)row*CC + c] = __float2half(v);
    }
    __syncthreads();
    {
        const float* rwe = rw + wid*CC;
        float acc = 0.f;
        #pragma unroll
        for (int i = 0; i < 32; i++) acc += sv[lane + i*32]*rwe[lane + i*32];
        #pragma unroll
        for (int o = 16; o > 0; o >>= 1) acc += __shfl_down_sync(0xffffffffu, acc, o);
        if (lane == 0) lg[wid] = acc;
    }
    __syncthreads();
    if (tid == 0) {
        int i0 = 0;
        #pragma unroll
        for (int e = 1; e < EE; e++) if (lg[e] > lg[i0]) i0 = e;
        int i1 = -1;
        #pragma unroll
        for (int e = 0; e < EE; e++) {
            if (e == i0) continue;
            if (i1 < 0 || lg[e] > lg[i1]) i1 = e;
        }
        float e1 = __expf(lg[i1] - lg[i0]);
        float sm = 1.f + e1;
        idx2[row*2]   = i0; idx2[row*2+1] = i1;
        wts2[row*2]   = 1.f/sm; wts2[row*2+1] = e1/sm;
        atomicAdd(&counts[i0], 1); atomicAdd(&counts[i1], 1);
    }
}

// ---------------- HMMA fp16 GEMM, 64x64 warp tiles, 3-stage; rope-fused fp16 epilogue ----------------
#define GBM 128
#define GBN 128
#define GBK 32
#define LDP 40
#define DSM_G (6*GBM*LDP*2)
__global__ __launch_bounds__(128)
void gemm16_k(const __half* __restrict__ A, const __half* __restrict__ Wb,
              float* __restrict__ Cout, __half* __restrict__ Cout16,
              int N, int K,
              const float* __restrict__ R,
              const int* __restrict__ perm,
              const int* __restrict__ poff,
              const float* __restrict__ rowscale,
              long wstride,
              const int* __restrict__ sperm,
              const float* __restrict__ ropeC,
              const float* __restrict__ ropeS) {
    extern __shared__ __half gsm[];
    __shared__ int rowsrc[GBM];

    int tid = threadIdx.x, wid = tid >> 5, lane = tid & 31;
    int tileN = blockIdx.x, tileM = blockIdx.y;
    int row0 = tileM*GBM;

    const __half* W = Wb;
    if (poff) {
        if (row0 >= poff[EE]) return;
        int e = 0;
        #pragma unroll
        for (int q2 = 1; q2 < EE; q2++) if (row0 >= poff[q2]) e = q2;
        W += (long)e * wstride;
    }
    if (tid < GBM) rowsrc[tid] = perm ? perm[row0 + tid] : (row0 + tid);
    __syncthreads();

    int warp_m = (wid & 1) * 64;
    int warp_n = (wid >> 1) * 64;

    unsigned sA[3], sB[3];
    #pragma unroll
    for (int i = 0; i < 3; i++) {
        sA[i] = s2u(gsm + i*GBM*LDP);
        sB[i] = s2u(gsm + (3 + i)*GBM*LDP);
    }

    auto load_stage = [&](int s) {
        int b = s % 3;
        long k0 = (long)s * GBK;
        #pragma unroll
        for (int c = 0; c < 4; c++) {
            int id = tid + c*128;
            int r = id >> 2, ch = id & 3;
            CPA16(sA[b] + (r*LDP + ch*8)*2, A + (long)rowsrc[r]*K + k0 + ch*8);
            CPA16(sB[b] + (r*LDP + ch*8)*2, W + (long)(tileN*GBN + r)*K + k0 + ch*8);
        }
        asm volatile("cp.async.commit_group;");
    };

    float acc[4][8][4] = {};
    int ns = K / GBK;
    load_stage(0);
    load_stage(1);

    for (int s = 0; s < ns; s++) {
        if (s + 1 < ns) asm volatile("cp.async.wait_group 1;");
        else            asm volatile("cp.async.wait_group 0;");
        __syncthreads();
        if (s + 2 < ns) load_stage(s + 2);
        int b = s % 3;
        #pragma unroll
        for (int kk = 0; kk < 2; kk++) {
            unsigned af[4][4], bf[4][4];
            #pragma unroll
            for (int mi = 0; mi < 4; mi++) {
                int r = warp_m + mi*16 + (lane & 15);
                int cH = kk*16 + ((lane >> 4) << 3);
                ldm_x4(af[mi][0], af[mi][1], af[mi][2], af[mi][3], sA[b] + (r*LDP + cH)*2);
            }
            #pragma unroll
            for (int pj = 0; pj < 4; pj++) {
                int n = warp_n + pj*16 + (lane & 7) + ((lane >> 4) << 3);
                int cH = kk*16 + (((lane >> 3) & 1) << 3);
                ldm_x4(bf[pj][0], bf[pj][1], bf[pj][2], bf[pj][3], sB[b] + (n*LDP + cH)*2);
            }
            #pragma unroll
            for (int mi = 0; mi < 4; mi++)
                #pragma unroll
                for (int nj = 0; nj < 8; nj++)
                    mma16816(acc[mi][nj][0], acc[mi][nj][1], acc[mi][nj][2], acc[mi][nj][3],
                             af[mi][0], af[mi][1], af[mi][2], af[mi][3],
                             bf[nj >> 1][(nj & 1)*2], bf[nj >> 1][(nj & 1)*2 + 1]);
        }
    }

    int lrow = lane >> 2;
    int lcol = (lane & 3) * 2;
    #pragma unroll
    for (int mi = 0; mi < 4; mi++) {
        #pragma unroll
        for (int half = 0; half < 2; half++) {
            int grow = row0 + warp_m + mi*16 + lrow + half*8;
            float sc = rowscale ? rowscale[grow] : 1.f;
            if (sperm) {
                if (sc != 0.f) {
                    int token = sperm[grow];
                    long obase = (long)token*N + tileN*GBN + warp_n;
                    #pragma unroll
                    for (int nj = 0; nj < 8; nj++) {
                        long off = obase + nj*8 + lcol;
                        atomicAdd(&Cout[off],     acc[mi][nj][half*2 + 0] * sc);
                        atomicAdd(&Cout[off + 1], acc[mi][nj][half*2 + 1] * sc);
                    }
                }
            } else if (ropeC) {
                int t = grow & (TT-1);
                long obase = (long)grow*N + tileN*GBN + warp_n;
                #pragma unroll
                for (int nj = 0; nj < 4; nj++) {
                    int colg = tileN*GBN + warp_n + nj*8 + lcol;
                    int seg = colg >> 10;            // 0=q,1=k,2=v
                    int d = colg & 63;               // 0..31 within head
                    float x1a = acc[mi][nj][half*2 + 0];
                    float x1b = acc[mi][nj][half*2 + 1];
                    float x2a = acc[mi][nj+4][half*2 + 0];
                    float x2b = acc[mi][nj+4][half*2 + 1];
                    if (seg < 2) {
                        const float* ct = ropeC + t*DD;
                        const float* st = ropeS + t*DD;
                        float c1a = ct[d],    c1b = ct[d+1];
                        float c2a = ct[d+32], c2b = ct[d+33];
                        float s1a = st[d],    s1b = st[d+1];
                        float s2a = st[d+32], s2b = st[d+33];
                        float o1a = x1a*c1a - x2a*s1a;
                        float o1b = x1b*c1b - x2b*s1b;
                        float o2a = x2a*c2a + x1a*s2a;
                        float o2b = x2b*c2b + x1b*s2b;
                        if (seg == 0) { o1a *= QSCALE; o1b *= QSCALE; o2a *= QSCALE; o2b *= QSCALE; }
                        x1a = o1a; x1b = o1b; x2a = o2a; x2b = o2b;
                    }
                    *(__half2*)(Cout16 + obase + nj*8 + lcol)        = __floats2half2_rn(x1a, x1b);
                    *(__half2*)(Cout16 + obase + (nj+4)*8 + lcol)    = __floats2half2_rn(x2a, x2b);
                }
            } else {
                long obase = (long)grow*N + tileN*GBN + warp_n;
                #pragma unroll
                for (int nj = 0; nj < 8; nj++) {
                    float vx = acc[mi][nj][half*2 + 0] * sc;
                    float vy = acc[mi][nj][half*2 + 1] * sc;
                    long off = obase + nj*8 + lcol;
                    if (Cout16) {
                        *(__half2*)(Cout16 + off) = __floats2half2_rn(vx, vy);
                    } else {
                        if (R) {
                            const float2 rv = *(const float2*)(R + off);
                            vx += rv.x; vy += rv.y;
                        }
                        float2 vv = { vx, vy };
                        *(float2*)(Cout + off) = vv;
                    }
                }
            }
        }
    }
}

// ---------------- fused MoE w1/w3 GEMM + silu*mul -> fp16, 3-stage ----------------
#define DSM_M (9*GBM*LDP*2)
__global__ __launch_bounds__(256)
void moe13_k(const __half* __restrict__ A, const __half* __restrict__ W1b,
             const __half* __restrict__ W3b, __half* __restrict__ G,
             const int* __restrict__ perm, const int* __restrict__ poff) {
    extern __shared__ __half sm[];
    __shared__ int rowsrc[GBM];

    int tid = threadIdx.x, wid = tid >> 5, lane = tid & 31;
    int tileN = blockIdx.x, tileM = blockIdx.y;
    int row0 = tileM*GBM;
    const int K = CC;

    if (row0 >= poff[EE]) return;
    int e = 0;
    #pragma unroll
    for (int q2 = 1; q2 < EE; q2++) if (row0 >= poff[q2]) e = q2;
    const __half* W1 = W1b + (long)e*HDIM*CC;
    const __half* W3 = W3b + (long)e*HDIM*CC;

    if (tid < GBM) rowsrc[tid] = perm[row0 + tid];
    __syncthreads();

    int warp_m = (wid >> 2) * 64;
    int warp_n = (wid & 3) * 32;

    unsigned sA[3], sB1[3], sB3[3];
    #pragma unroll
    for (int i = 0; i < 3; i++) {
        sA[i]  = s2u(sm + i*GBM*LDP);
        sB1[i] = s2u(sm + (3 + i)*GBM*LDP);
        sB3[i] = s2u(sm + (6 + i)*GBM*LDP);
    }

    auto load_stage = [&](int s) {
        int b = s % 3;
        long k0 = (long)s * GBK;
        #pragma unroll
        for (int c = 0; c < 2; c++) {
            int id = tid + c*256;
            int r = id >> 2, ch = id & 3;
            CPA16(sA[b]  + (r*LDP + ch*8)*2, A  + (long)rowsrc[r]*K + k0 + ch*8);
            CPA16(sB1[b] + (r*LDP + ch*8)*2, W1 + (long)(tileN*GBN + r)*K + k0 + ch*8);
            CPA16(sB3[b] + (r*LDP + ch*8)*2, W3 + (long)(tileN*GBN + r)*K + k0 + ch*8);
        }
        asm volatile("cp.async.commit_group;");
    };

    float a1[4][4][4] = {};
    float a3[4][4][4] = {};
    int ns = K / GBK;
    load_stage(0);
    load_stage(1);

    for (int s = 0; s < ns; s++) {
        if (s + 1 < ns) asm volatile("cp.async.wait_group 1;");
        else            asm volatile("cp.async.wait_group 0;");
        __syncthreads();
        if (s + 2 < ns) load_stage(s + 2);
        int b = s % 3;
        #pragma unroll
        for (int kk = 0; kk < 2; kk++) {
            unsigned af[4][4], b1f[2][4], b3f[2][4];
            #pragma unroll
            for (int mi = 0; mi < 4; mi++) {
                int r = warp_m + mi*16 + (lane & 15);
                int cH = kk*16 + ((lane >> 4) << 3);
                ldm_x4(af[mi][0], af[mi][1], af[mi][2], af[mi][3], sA[b] + (r*LDP + cH)*2);
            }
            #pragma unroll
            for (int pj = 0; pj < 2; pj++) {
                int n = warp_n + pj*16 + (lane & 7) + ((lane >> 4) << 3);
                int cH = kk*16 + (((lane >> 3) & 1) << 3);
                ldm_x4(b1f[pj][0], b1f[pj][1], b1f[pj][2], b1f[pj][3], sB1[b] + (n*LDP + cH)*2);
                ldm_x4(b3f[pj][0], b3f[pj][1], b3f[pj][2], b3f[pj][3], sB3[b] + (n*LDP + cH)*2);
            }
            #pragma unroll
            for (int mi = 0; mi < 4; mi++)
                #pragma unroll
                for (int nj = 0; nj < 4; nj++) {
                    mma16816(a1[mi][nj][0], a1[mi][nj][1], a1[mi][nj][2], a1[mi][nj][3],
                             af[mi][0], af[mi][1], af[mi][2], af[mi][3],
                             b1f[nj >> 1][(nj & 1)*2], b1f[nj >> 1][(nj & 1)*2 + 1]);
                    mma16816(a3[mi][nj][0], a3[mi][nj][1], a3[mi][nj][2], a3[mi][nj][3],
                             af[mi][0], af[mi][1], af[mi][2], af[mi][3],
                             b3f[nj >> 1][(nj & 1)*2], b3f[nj >> 1][(nj & 1)*2 + 1]);
                }
        }
    }

    int lrow = lane >> 2;
    int lcol = (lane & 3) * 2;
    #pragma unroll
    for (int mi = 0; mi < 4; mi++) {
        #pragma unroll
        for (int half = 0; half < 2; half++) {
            int grow = row0 + warp_m + mi*16 + lrow + half*8;
            long obase = (long)grow*HDIM + tileN*GBN + warp_n;
            #pragma unroll
            for (int nj = 0; nj < 4; nj++) {
                float u0 = a1[mi][nj][half*2 + 0];
                float u1 = a1[mi][nj][half*2 + 1];
                float w0 = a3[mi][nj][half*2 + 0];
                float w1 = a3[mi][nj][half*2 + 1];
                float g0 = u0 / (1.f + __expf(-u0)) * w0;
                float g1 = u1 / (1.f + __expf(-u1)) * w1;
                *(__half2*)(G + obase + nj*8 + lcol) = __floats2half2_rn(g0, g1);
            }
        }
    }
}

// ---------------- FlashAttention-2 HMMA causal attention: 3-deep KV ring, 1 barrier/tile ----------------
#define ASTR 72
#define QKVS (3*CC)
#define FQT 128
#define DSM_F ((FQT*ASTR + 6*64*ASTR)*2)
__global__ __launch_bounds__(256)
void fattn_k(const __half* __restrict__ qkv, __half* __restrict__ y) {
    extern __shared__ __half fsm[];
    int qb = (int)gridDim.x - 1 - (int)blockIdx.x;
    int h = blockIdx.y, b = blockIdx.z;
    int tid = threadIdx.x, wid = tid >> 5, lane = tid & 31;

    unsigned uQ = s2u(fsm);
    unsigned uK[3] = { s2u(fsm + FQT*ASTR),
                       s2u(fsm + FQT*ASTR + 64*ASTR),
                       s2u(fsm + FQT*ASTR + 2*64*ASTR) };
    unsigned uV[3] = { s2u(fsm + FQT*ASTR + 3*64*ASTR),
                       s2u(fsm + FQT*ASTR + 4*64*ASTR),
                       s2u(fsm + FQT*ASTR + 5*64*ASTR) };

    long qbase = (long)(b*TT + qb*FQT)*QKVS + h*DD;
    #pragma unroll
    for (int c = 0; c < 4; c++) {
        int id = tid + c*256;
        int r = id >> 3, ch = id & 7;
        CPA16(uQ + (r*ASTR + ch*8)*2, qkv + qbase + (long)r*QKVS + ch*8);
    }
    asm volatile("cp.async.commit_group;");

    auto load_kv = [&](int s) {
        int bb = s % 3;
        long kvb = (long)(b*TT + s*64)*QKVS + h*DD + CC;
        #pragma unroll
        for (int c = 0; c < 2; c++) {
            int id = tid + c*256;
            int r = id >> 3, ch = id & 7;
            CPA16(uK[bb] + (r*ASTR + ch*8)*2, qkv + kvb + (long)r*QKVS + ch*8);
            CPA16(uV[bb] + (r*ASTR + ch*8)*2, qkv + kvb + CC + (long)r*QKVS + ch*8);
        }
        asm volatile("cp.async.commit_group;");
    };

    int nkt = 2*qb + 2;
    load_kv(0);
    if (nkt > 1) load_kv(1);

    // first wait covers Q + tile0 (FIFO group completion)
    bool qloaded = false;
    float m0 = -1e30f, m1 = -1e30f, l0 = 0.f, l1 = 0.f;
    float oa[8][4] = {};
    unsigned qa[4][4];

    for (int kt = 0; kt < nkt; kt++) {
        if (kt + 1 < nkt) asm volatile("cp.async.wait_group 1;");
        else              asm volatile("cp.async.wait_group 0;");
        __syncthreads();
        if (kt + 2 < nkt) load_kv(kt + 2);
        if (!qloaded) {
            #pragma unroll
            for (int kk = 0; kk < 4; kk++) {
                int r = wid*16 + (lane & 15);
                int cH = kk*16 + ((lane >> 4) << 3);
                ldm_x4(qa[kk][0], qa[kk][1], qa[kk][2], qa[kk][3], uQ + (r*ASTR + cH)*2);
            }
            qloaded = true;
        }
        int bb = kt % 3;

        float sc[8][4] = {};
        #pragma unroll
        for (int kk = 0; kk < 4; kk++) {
            unsigned bf[4][4];
            #pragma unroll
            for (int pj = 0; pj < 4; pj++) {
                int n = pj*16 + (lane & 7) + ((lane >> 4) << 3);
                int cH = kk*16 + (((lane >> 3) & 1) << 3);
                ldm_x4(bf[pj][0], bf[pj][1], bf[pj][2], bf[pj][3], uK[bb] + (n*ASTR + cH)*2);
            }
            #pragma unroll
            for (int nj = 0; nj < 8; nj++)
                mma16816(sc[nj][0], sc[nj][1], sc[nj][2], sc[nj][3],
                         qa[kk][0], qa[kk][1], qa[kk][2], qa[kk][3],
                         bf[nj >> 1][(nj & 1)*2], bf[nj >> 1][(nj & 1)*2 + 1]);
        }

        if (kt >= 2*qb) {
            int rg = qb*FQT + wid*16 + (lane >> 2);
            #pragma unroll
            for (int nj = 0; nj < 8; nj++) {
                int cg = kt*64 + nj*8 + (lane & 3)*2;
                if (cg     > rg)   sc[nj][0] = -1e30f;
                if (cg + 1 > rg)   sc[nj][1] = -1e30f;
                if (cg     > rg+8) sc[nj][2] = -1e30f;
                if (cg + 1 > rg+8) sc[nj][3] = -1e30f;
            }
        }

        float rm0 = -1e30f, rm1 = -1e30f;
        #pragma unroll
        for (int nj = 0; nj < 8; nj++) {
            rm0 = fmaxf(rm0, fmaxf(sc[nj][0], sc[nj][1]));
            rm1 = fmaxf(rm1, fmaxf(sc[nj][2], sc[nj][3]));
        }
        rm0 = fmaxf(rm0, __shfl_xor_sync(0xffffffffu, rm0, 1));
        rm0 = fmaxf(rm0, __shfl_xor_sync(0xffffffffu, rm0, 2));
        rm1 = fmaxf(rm1, __shfl_xor_sync(0xffffffffu, rm1, 1));
        rm1 = fmaxf(rm1, __shfl_xor_sync(0xffffffffu, rm1, 2));
        float mn0 = fmaxf(m0, rm0), mn1 = fmaxf(m1, rm1);
        float corr0 = exp2f(m0 - mn0), corr1 = exp2f(m1 - mn1);
        m0 = mn0; m1 = mn1;

        unsigned pa[4][4];
        float ps0 = 0.f, ps1 = 0.f;
        #pragma unroll
        for (int j = 0; j < 4; j++) {
            float p00 = exp2f(sc[2*j][0]   - m0), p01 = exp2f(sc[2*j][1]   - m0);
            float p02 = exp2f(sc[2*j][2]   - m1), p03 = exp2f(sc[2*j][3]   - m1);
            float p10 = exp2f(sc[2*j+1][0] - m0), p11 = exp2f(sc[2*j+1][1] - m0);
            float p12 = exp2f(sc[2*j+1][2] - m1), p13 = exp2f(sc[2*j+1][3] - m1);
            ps0 += p00 + p01 + p10 + p11;
            ps1 += p02 + p03 + p12 + p13;
            __half2 h0 = __floats2half2_rn(p00, p01);
            __half2 h1 = __floats2half2_rn(p02, p03);
            __half2 h2 = __floats2half2_rn(p10, p11);
            __half2 h3 = __floats2half2_rn(p12, p13);
            pa[j][0] = *(unsigned*)&h0;
            pa[j][1] = *(unsigned*)&h1;
            pa[j][2] = *(unsigned*)&h2;
            pa[j][3] = *(unsigned*)&h3;
        }
        ps0 += __shfl_xor_sync(0xffffffffu, ps0, 1);
        ps0 += __shfl_xor_sync(0xffffffffu, ps0, 2);
        ps1 += __shfl_xor_sync(0xffffffffu, ps1, 1);
        ps1 += __shfl_xor_sync(0xffffffffu, ps1, 2);
        l0 = l0*corr0 + ps0;
        l1 = l1*corr1 + ps1;

        #pragma unroll
        for (int nj = 0; nj < 8; nj++) {
            oa[nj][0] *= corr0; oa[nj][1] *= corr0;
            oa[nj][2] *= corr1; oa[nj][3] *= corr1;
        }

        #pragma unroll
        for (int j = 0; j < 4; j++) {
            unsigned vf[4][4];
            #pragma unroll
            for (int pd = 0; pd < 4; pd++) {
                int r = j*16 + (lane & 15);
                int cH = pd*16 + ((lane >> 4) << 3);
                ldm_x4t(vf[pd][0], vf[pd][1], vf[pd][2], vf[pd][3], uV[bb] + (r*ASTR + cH)*2);
            }
            #pragma unroll
            for (int dn = 0; dn < 8; dn++)
                mma16816(oa[dn][0], oa[dn][1], oa[dn][2], oa[dn][3],
                         pa[j][0], pa[j][1], pa[j][2], pa[j][3],
                         vf[dn >> 1][(dn & 1)*2], vf[dn >> 1][(dn & 1)*2 + 1]);
        }
        // no trailing __syncthreads: 3-deep ring guarantees the next writer of this
        // buffer (tile kt+3, issued after the barrier of tile kt+1) cannot race these reads
    }

    float il0 = 1.f/l0, il1 = 1.f/l1;
    int r0 = qb*FQT + wid*16 + (lane >> 2);
    #pragma unroll
    for (int dn = 0; dn < 8; dn++) {
        int col = dn*8 + (lane & 3)*2;
        long o0 = ((long)(b*TT + r0)*HH + h)*DD + col;
        long o1 = ((long)(b*TT + r0 + 8)*HH + h)*DD + col;
        *(__half2*)(y + o0) = __floats2half2_rn(oa[dn][0]*il0, oa[dn][1]*il0);
        *(__half2*)(y + o1) = __floats2half2_rn(oa[dn][2]*il1, oa[dn][3]*il1);
    }
}

// ---------------- scatter with fused offset computation ----------------
__global__ void scatter_k(const int* __restrict__ idx2, const float* __restrict__ wts2,
                          int* __restrict__ cursor, const int* __restrict__ counts,
                          int* __restrict__ perm, float* __restrict__ gatew,
                          int* __restrict__ poff) {
    __shared__ int spoff[EE+1];
    if (threadIdx.x == 0) {
        int o = 0;
        #pragma unroll
        for (int e = 0; e < EE; e++) {
            spoff[e] = o;
            o += ((counts[e] + 127)/128)*128;
        }
        spoff[EE] = o;
        if (blockIdx.x == 0) {
            #pragma unroll
            for (int e = 0; e <= EE; e++) poff[e] = spoff[e];
        }
    }
    __syncthreads();
    int t = blockIdx.x*blockDim.x + threadIdx.x;
    if (t >= M0) return;
    for (int kk = 0; kk < 2; kk++) {
        int e = idx2[t*2 + kk];
        int pos = atomicAdd(&cursor[e], 1);
        int r = spoff[e] + pos;
        perm[r] = t; gatew[r] = wts2[t*2 + kk];
    }
}

// ---------------- launch ----------------
static void* sym(const void* s) { void* p = nullptr; cudaGetSymbolAddress(&p, s); return p; }

extern "C" void kernel_launch(void* const* d_in, const int* in_sizes, int n_in,
                              void* d_out, int out_size) {
    const float* x    = (const float*)d_in[0];
    const float* rc   = (const float*)d_in[1];
    const float* rs   = (const float*)d_in[2];
    const float* anw  = (const float*)d_in[3];
    const float* qw   = (const float*)d_in[4];
    const float* kw   = (const float*)d_in[5];
    const float* vw   = (const float*)d_in[6];
    const float* ow   = (const float*)d_in[7];
    const float* fnw  = (const float*)d_in[8];
    const float* rw   = (const float*)d_in[9];
    const float* w1   = (const float*)d_in[10];
    const float* w2   = (const float*)d_in[11];
    const float* w3   = (const float*)d_in[12];
    float* out = (float*)d_out;

    __half* h16   = (__half*)sym(g_h16);
    __half* qkv16 = (__half*)sym(g_qkv16);
    __half* y16   = (__half*)sym(g_y16);
    __half* hn16  = (__half*)sym(g_hn16);
    __half* gb16  = (__half*)sym(g_gb16);
    __half* w16   = (__half*)sym(g_w16all);
    __half* wqkv16= w16;
    __half* ow16  = w16 + OFF_OW;
    __half* w116  = w16 + OFF_W1;
    __half* w216  = w16 + OFF_W2;
    __half* w316  = w16 + OFF_W3;
    int*   counts = (int*)sym(g_counts);
    int*   cursor = (int*)sym(g_cursor);
    int*   poff   = (int*)sym(g_poff);
    int*   perm   = (int*)sym(g_perm);
    float* gatew  = (float*)sym(g_gatew);
    int*   idx2   = (int*)sym(g_idx2);
    float* wts2   = (float*)sym(g_wts2);

    cudaFuncSetAttribute(gemm16_k, cudaFuncAttributeMaxDynamicSharedMemorySize, DSM_G);
    cudaFuncSetAttribute(moe13_k, cudaFuncAttributeMaxDynamicSharedMemorySize, DSM_M);
    cudaFuncSetAttribute(fattn_k, cudaFuncAttributeMaxDynamicSharedMemorySize, DSM_F);

    // 0) fused weight conversion + MoE bookkeeping init (counts, cursor, perm, gatew)
    int ncv = 4*N4C + 3*N4E;
    convw_k<<<(ncv + 255)/256, 256>>>((const float4*)qw, (const float4*)kw, (const float4*)vw,
                                      (const float4*)ow, (const float4*)w1, (const float4*)w2,
                                      (const float4*)w3, (__half2*)w16, counts, cursor, perm, gatew);
    // 1) attn rmsnorm (fp16 out)
    rmsnorm_k<<<M0, 256>>>(x, anw, h16);
    // 2) fused QKV projection with rope epilogue (fp16 out, q in log2 domain)
    gemm16_k<<<dim3(3*CC/GBN, M0/GBM), 128, DSM_G>>>(h16, wqkv16, nullptr, qkv16, 3*CC, CC,
                                                     nullptr, nullptr, nullptr, nullptr, 0, nullptr, rc, rs);
    // 3) causal flash attention (3-deep KV ring, one barrier per tile)
    fattn_k<<<dim3(TT/FQT, HH, BB), 256, DSM_F>>>(qkv16, y16);
    // 4) output projection + residual -> out
    gemm16_k<<<dim3(CC/GBN, M0/GBM), 128, DSM_G>>>(y16, ow16, out, nullptr, CC, CC,
                                                   x, nullptr, nullptr, nullptr, 0, nullptr, nullptr, nullptr);
    // 5) fused ffn rmsnorm + router
    rmsnorm_router_k<<<M0, 256>>>(out, fnw, hn16, rw, idx2, wts2, counts);
    // 6) scatter with fused offsets
    scatter_k<<<(M0 + 255)/256, 256>>>(idx2, wts2, cursor, counts, perm, gatew, poff);
    // 7) fused expert up-projection + silu*mul
    moe13_k<<<dim3(HDIM/GBN, MG/GBM), 256, DSM_M>>>(hn16, w116, w316, gb16, perm, poff);
    //    down-projection: gate-scaled atomic scatter into out
    gemm16_k<<<dim3(CC/GBN, MG/GBM), 128, DSM_G>>>(gb16, w216, out, nullptr, CC, HDIM,
                                                   nullptr, nullptr, poff, gatew, (long)CC*HDIM, perm, nullptr, nullptr);
}

// round 15
// speedup vs baseline: 1.0241x; 1.0125x over previous
#include <cuda_runtime.h>
#include <cuda_fp16.h>
#include <cstdint>
#include <stdint.h>
#include <math.h>

// ---------------- problem constants ----------------
#define BB 2
#define TT 2048
#define CC 1024
#define HH 16
#define DD 64
#define EE 8
#define HDIM 1536
#define M0 (BB*TT)
#define MG 9216
#define EPSV 1e-6f

#define N4C (CC*CC/4)
#define N4E (EE*HDIM*CC/4)
#define NCV (4*N4C + 3*N4E)
#define CONVB ((NCV + 255)/256)
#define OFF_OW (3*CC*CC)
#define OFF_W1 (4*CC*CC)
#define OFF_W2 (OFF_W1 + EE*HDIM*CC)
#define OFF_W3 (OFF_W2 + EE*HDIM*CC)
#define W16TOT (OFF_W3 + EE*HDIM*CC)

// ---------------- device scratch ----------------
__device__ __half g_h16 [M0*CC];
__device__ __half g_qkv16[M0*3*CC];
__device__ __half g_y16 [M0*CC];
__device__ __half g_hn16[M0*CC];
__device__ __half g_gb16[MG*HDIM];
__device__ __half g_w16all[W16TOT];
__device__ int    g_counts[EE];
__device__ int    g_cursor[EE];
__device__ int    g_poff[EE+1];
__device__ int    g_perm[MG];
__device__ float  g_gatew[MG];
__device__ int    g_idx2[M0*2];
__device__ float  g_wts2[M0*2];

// ---------------- PTX helpers ----------------
__device__ __forceinline__ unsigned s2u(const void* p) {
    unsigned a;
    asm("{ .reg .u64 t; cvta.to.shared.u64 t, %1; cvt.u32.u64 %0, t; }" : "=r"(a) : "l"(p));
    return a;
}
__device__ __forceinline__ void ldm_x4(unsigned& r0, unsigned& r1, unsigned& r2, unsigned& r3, unsigned a) {
    asm volatile("ldmatrix.sync.aligned.m8n8.x4.shared.b16 {%0,%1,%2,%3}, [%4];"
                 : "=r"(r0), "=r"(r1), "=r"(r2), "=r"(r3) : "r"(a));
}
__device__ __forceinline__ void ldm_x4t(unsigned& r0, unsigned& r1, unsigned& r2, unsigned& r3, unsigned a) {
    asm volatile("ldmatrix.sync.aligned.m8n8.x4.trans.shared.b16 {%0,%1,%2,%3}, [%4];"
                 : "=r"(r0), "=r"(r1), "=r"(r2), "=r"(r3) : "r"(a));
}
__device__ __forceinline__ void mma16816(float& d0, float& d1, float& d2, float& d3,
                                         unsigned a0, unsigned a1, unsigned a2, unsigned a3,
                                         unsigned b0, unsigned b1) {
    asm volatile("mma.sync.aligned.m16n8k16.row.col.f32.f16.f16.f32 "
                 "{%0,%1,%2,%3}, {%4,%5,%6,%7}, {%8,%9}, {%0,%1,%2,%3};"
                 : "+f"(d0), "+f"(d1), "+f"(d2), "+f"(d3)
                 : "r"(a0), "r"(a1), "r"(a2), "r"(a3), "r"(b0), "r"(b1));
}
#define CPA16(dst, src) asm volatile("cp.async.cg.shared.global [%0], [%1], 16;" :: "r"(dst), "l"(src))

#define QSCALE (0.125f * 1.4426950408889634f)   // 1/sqrt(D) * log2(e)

// ---------------- fused: weight conversion + MoE init + attn RMSNorm (partitioned grid) ----------------
__global__ void convw_rms_k(const float4* __restrict__ q, const float4* __restrict__ k,
                            const float4* __restrict__ v, const float4* __restrict__ o,
                            const float4* __restrict__ w1, const float4* __restrict__ w2,
                            const float4* __restrict__ w3, __half2* __restrict__ dst,
                            int* __restrict__ counts, int* __restrict__ cursor,
                            int* __restrict__ perm, float* __restrict__ gatew,
                            const float* __restrict__ x, const float* __restrict__ anw,
                            __half* __restrict__ h16) {
    if (blockIdx.x < CONVB) {
        int i = blockIdx.x*256 + threadIdx.x;
        if (i < EE) { counts[i] = 0; cursor[i] = 0; }
        if (i < MG) { perm[i] = 0; gatew[i] = 0.f; }
        if (i >= NCV) return;
        const float4* s;
        long base;
        if (i < 4*N4C) {
            int seg = i / N4C, off = i - seg*N4C;
            s = (seg == 0 ? q : seg == 1 ? k : seg == 2 ? v : o) + off;
            base = (long)seg*N4C + off;
        } else {
            int j = i - 4*N4C;
            int seg = j / N4E, off = j - seg*N4E;
            s = (seg == 0 ? w1 : seg == 1 ? w2 : w3) + off;
            base = (long)4*N4C + (long)seg*N4E + off;
        }
        float4 val = *s;
        dst[base*2]   = __floats2half2_rn(val.x, val.y);
        dst[base*2+1] = __floats2half2_rn(val.z, val.w);
    } else {
        int row = blockIdx.x - CONVB;
        const float* xr = x + (long)row*CC;
        __shared__ float red[256];
        float s = 0.f;
        #pragma unroll
        for (int j = 0; j < 4; j++) { float vv = xr[threadIdx.x + j*256]; s += vv*vv; }
        red[threadIdx.x] = s; __syncthreads();
        for (int st = 128; st > 0; st >>= 1) {
            if (threadIdx.x < st) red[threadIdx.x] += red[threadIdx.x+st];
            __syncthreads();
        }
        float inv = rsqrtf(red[0]/(float)CC + EPSV);
        #pragma unroll
        for (int j = 0; j < 4; j++) {
            int c = threadIdx.x + j*256;
            h16[(long)row*CC + c] = __float2half(anw[c]*xr[c]*inv);
        }
    }
}

// ---------------- fused ffn RMSNorm + router (per-row block) ----------------
__global__ void rmsnorm_router_k(const float* __restrict__ x, const float* __restrict__ w,
                                 __half* __restrict__ o16, const float* __restrict__ rw,
                                 int* __restrict__ idx2, float* __restrict__ wts2,
                                 int* __restrict__ counts) {
    int row = blockIdx.x;
    int tid = threadIdx.x, wid = tid >> 5, lane = tid & 31;
    const float* xr = x + (long)row*CC;
    __shared__ float sv[CC];
    __shared__ float red[256];
    __shared__ float lg[EE];
    float s = 0.f;
    #pragma unroll
    for (int j = 0; j < 4; j++) { float v = xr[tid + j*256]; s += v*v; }
    red[tid] = s; __syncthreads();
    for (int st = 128; st > 0; st >>= 1) {
        if (tid < st) red[tid] += red[tid+st];
        __syncthreads();
    }
    float inv = rsqrtf(red[0]/(float)CC + EPSV);
    #pragma unroll
    for (int j = 0; j < 4; j++) {
        int c = tid + j*256;
        float v = w[c]*xr[c]*inv;
        sv[c] = v;
        o16[(long)row*CC + c] = __float2half(v);
    }
    __syncthreads();
    {
        const float* rwe = rw + wid*CC;
        float acc = 0.f;
        #pragma unroll
        for (int i = 0; i < 32; i++) acc += sv[lane + i*32]*rwe[lane + i*32];
        #pragma unroll
        for (int o = 16; o > 0; o >>= 1) acc += __shfl_down_sync(0xffffffffu, acc, o);
        if (lane == 0) lg[wid] = acc;
    }
    __syncthreads();
    if (tid == 0) {
        int i0 = 0;
        #pragma unroll
        for (int e = 1; e < EE; e++) if (lg[e] > lg[i0]) i0 = e;
        int i1 = -1;
        #pragma unroll
        for (int e = 0; e < EE; e++) {
            if (e == i0) continue;
            if (i1 < 0 || lg[e] > lg[i1]) i1 = e;
        }
        float e1 = __expf(lg[i1] - lg[i0]);
        float sm = 1.f + e1;
        idx2[row*2]   = i0; idx2[row*2+1] = i1;
        wts2[row*2]   = 1.f/sm; wts2[row*2+1] = e1/sm;
        atomicAdd(&counts[i0], 1); atomicAdd(&counts[i1], 1);
    }
}

// ---------------- HMMA fp16 GEMM, 64x64 warp tiles, 3-stage; rope-fused fp16 epilogue ----------------
#define GBM 128
#define GBN 128
#define GBK 32
#define LDP 40
#define DSM_G (6*GBM*LDP*2)
__global__ __launch_bounds__(128)
void gemm16_k(const __half* __restrict__ A, const __half* __restrict__ Wb,
              float* __restrict__ Cout, __half* __restrict__ Cout16,
              int N, int K,
              const float* __restrict__ R,
              const int* __restrict__ perm,
              const int* __restrict__ poff,
              const float* __restrict__ rowscale,
              long wstride,
              const int* __restrict__ sperm,
              const float* __restrict__ ropeC,
              const float* __restrict__ ropeS) {
    extern __shared__ __half gsm[];
    __shared__ int rowsrc[GBM];

    int tid = threadIdx.x, wid = tid >> 5, lane = tid & 31;
    int tileN = blockIdx.x, tileM = blockIdx.y;
    int row0 = tileM*GBM;

    const __half* W = Wb;
    if (poff) {
        if (row0 >= poff[EE]) return;
        int e = 0;
        #pragma unroll
        for (int q2 = 1; q2 < EE; q2++) if (row0 >= poff[q2]) e = q2;
        W += (long)e * wstride;
    }
    if (tid < GBM) rowsrc[tid] = perm ? perm[row0 + tid] : (row0 + tid);
    __syncthreads();

    int warp_m = (wid & 1) * 64;
    int warp_n = (wid >> 1) * 64;

    unsigned sA[3], sB[3];
    #pragma unroll
    for (int i = 0; i < 3; i++) {
        sA[i] = s2u(gsm + i*GBM*LDP);
        sB[i] = s2u(gsm + (3 + i)*GBM*LDP);
    }

    auto load_stage = [&](int s) {
        int b = s % 3;
        long k0 = (long)s * GBK;
        #pragma unroll
        for (int c = 0; c < 4; c++) {
            int id = tid + c*128;
            int r = id >> 2, ch = id & 3;
            CPA16(sA[b] + (r*LDP + ch*8)*2, A + (long)rowsrc[r]*K + k0 + ch*8);
            CPA16(sB[b] + (r*LDP + ch*8)*2, W + (long)(tileN*GBN + r)*K + k0 + ch*8);
        }
        asm volatile("cp.async.commit_group;");
    };

    float acc[4][8][4] = {};
    int ns = K / GBK;
    load_stage(0);
    load_stage(1);

    for (int s = 0; s < ns; s++) {
        if (s + 1 < ns) asm volatile("cp.async.wait_group 1;");
        else            asm volatile("cp.async.wait_group 0;");
        __syncthreads();
        if (s + 2 < ns) load_stage(s + 2);
        int b = s % 3;
        #pragma unroll
        for (int kk = 0; kk < 2; kk++) {
            unsigned af[4][4], bf[4][4];
            #pragma unroll
            for (int mi = 0; mi < 4; mi++) {
                int r = warp_m + mi*16 + (lane & 15);
                int cH = kk*16 + ((lane >> 4) << 3);
                ldm_x4(af[mi][0], af[mi][1], af[mi][2], af[mi][3], sA[b] + (r*LDP + cH)*2);
            }
            #pragma unroll
            for (int pj = 0; pj < 4; pj++) {
                int n = warp_n + pj*16 + (lane & 7) + ((lane >> 4) << 3);
                int cH = kk*16 + (((lane >> 3) & 1) << 3);
                ldm_x4(bf[pj][0], bf[pj][1], bf[pj][2], bf[pj][3], sB[b] + (n*LDP + cH)*2);
            }
            #pragma unroll
            for (int mi = 0; mi < 4; mi++)
                #pragma unroll
                for (int nj = 0; nj < 8; nj++)
                    mma16816(acc[mi][nj][0], acc[mi][nj][1], acc[mi][nj][2], acc[mi][nj][3],
                             af[mi][0], af[mi][1], af[mi][2], af[mi][3],
                             bf[nj >> 1][(nj & 1)*2], bf[nj >> 1][(nj & 1)*2 + 1]);
        }
    }

    int lrow = lane >> 2;
    int lcol = (lane & 3) * 2;
    #pragma unroll
    for (int mi = 0; mi < 4; mi++) {
        #pragma unroll
        for (int half = 0; half < 2; half++) {
            int grow = row0 + warp_m + mi*16 + lrow + half*8;
            float sc = rowscale ? rowscale[grow] : 1.f;
            if (sperm) {
                if (sc != 0.f) {
                    int token = sperm[grow];
                    long obase = (long)token*N + tileN*GBN + warp_n;
                    #pragma unroll
                    for (int nj = 0; nj < 8; nj++) {
                        long off = obase + nj*8 + lcol;
                        atomicAdd(&Cout[off],     acc[mi][nj][half*2 + 0] * sc);
                        atomicAdd(&Cout[off + 1], acc[mi][nj][half*2 + 1] * sc);
                    }
                }
            } else if (ropeC) {
                int t = grow & (TT-1);
                long obase = (long)grow*N + tileN*GBN + warp_n;
                #pragma unroll
                for (int nj = 0; nj < 4; nj++) {
                    int colg = tileN*GBN + warp_n + nj*8 + lcol;
                    int seg = colg >> 10;            // 0=q,1=k,2=v
                    int d = colg & 63;               // 0..31 within head
                    float x1a = acc[mi][nj][half*2 + 0];
                    float x1b = acc[mi][nj][half*2 + 1];
                    float x2a = acc[mi][nj+4][half*2 + 0];
                    float x2b = acc[mi][nj+4][half*2 + 1];
                    if (seg < 2) {
                        const float* ct = ropeC + t*DD;
                        const float* st = ropeS + t*DD;
                        float c1a = ct[d],    c1b = ct[d+1];
                        float c2a = ct[d+32], c2b = ct[d+33];
                        float s1a = st[d],    s1b = st[d+1];
                        float s2a = st[d+32], s2b = st[d+33];
                        float o1a = x1a*c1a - x2a*s1a;
                        float o1b = x1b*c1b - x2b*s1b;
                        float o2a = x2a*c2a + x1a*s2a;
                        float o2b = x2b*c2b + x1b*s2b;
                        if (seg == 0) { o1a *= QSCALE; o1b *= QSCALE; o2a *= QSCALE; o2b *= QSCALE; }
                        x1a = o1a; x1b = o1b; x2a = o2a; x2b = o2b;
                    }
                    *(__half2*)(Cout16 + obase + nj*8 + lcol)        = __floats2half2_rn(x1a, x1b);
                    *(__half2*)(Cout16 + obase + (nj+4)*8 + lcol)    = __floats2half2_rn(x2a, x2b);
                }
            } else {
                long obase = (long)grow*N + tileN*GBN + warp_n;
                #pragma unroll
                for (int nj = 0; nj < 8; nj++) {
                    float vx = acc[mi][nj][half*2 + 0] * sc;
                    float vy = acc[mi][nj][half*2 + 1] * sc;
                    long off = obase + nj*8 + lcol;
                    if (Cout16) {
                        *(__half2*)(Cout16 + off) = __floats2half2_rn(vx, vy);
                    } else {
                        if (R) {
                            const float2 rv = *(const float2*)(R + off);
                            vx += rv.x; vy += rv.y;
                        }
                        float2 vv = { vx, vy };
                        *(float2*)(Cout + off) = vv;
                    }
                }
            }
        }
    }
}

// ---------------- fused MoE w1/w3 GEMM + silu*mul -> fp16, 3-stage ----------------
#define DSM_M (9*GBM*LDP*2)
__global__ __launch_bounds__(256)
void moe13_k(const __half* __restrict__ A, const __half* __restrict__ W1b,
             const __half* __restrict__ W3b, __half* __restrict__ G,
             const int* __restrict__ perm, const int* __restrict__ poff) {
    extern __shared__ __half sm[];
    __shared__ int rowsrc[GBM];

    int tid = threadIdx.x, wid = tid >> 5, lane = tid & 31;
    int tileN = blockIdx.x, tileM = blockIdx.y;
    int row0 = tileM*GBM;
    const int K = CC;

    if (row0 >= poff[EE]) return;
    int e = 0;
    #pragma unroll
    for (int q2 = 1; q2 < EE; q2++) if (row0 >= poff[q2]) e = q2;
    const __half* W1 = W1b + (long)e*HDIM*CC;
    const __half* W3 = W3b + (long)e*HDIM*CC;

    if (tid < GBM) rowsrc[tid] = perm[row0 + tid];
    __syncthreads();

    int warp_m = (wid >> 2) * 64;
    int warp_n = (wid & 3) * 32;

    unsigned sA[3], sB1[3], sB3[3];
    #pragma unroll
    for (int i = 0; i < 3; i++) {
        sA[i]  = s2u(sm + i*GBM*LDP);
        sB1[i] = s2u(sm + (3 + i)*GBM*LDP);
        sB3[i] = s2u(sm + (6 + i)*GBM*LDP);
    }

    auto load_stage = [&](int s) {
        int b = s % 3;
        long k0 = (long)s * GBK;
        #pragma unroll
        for (int c = 0; c < 2; c++) {
            int id = tid + c*256;
            int r = id >> 2, ch = id & 3;
            CPA16(sA[b]  + (r*LDP + ch*8)*2, A  + (long)rowsrc[r]*K + k0 + ch*8);
            CPA16(sB1[b] + (r*LDP + ch*8)*2, W1 + (long)(tileN*GBN + r)*K + k0 + ch*8);
            CPA16(sB3[b] + (r*LDP + ch*8)*2, W3 + (long)(tileN*GBN + r)*K + k0 + ch*8);
        }
        asm volatile("cp.async.commit_group;");
    };

    float a1[4][4][4] = {};
    float a3[4][4][4] = {};
    int ns = K / GBK;
    load_stage(0);
    load_stage(1);

    for (int s = 0; s < ns; s++) {
        if (s + 1 < ns) asm volatile("cp.async.wait_group 1;");
        else            asm volatile("cp.async.wait_group 0;");
        __syncthreads();
        if (s + 2 < ns) load_stage(s + 2);
        int b = s % 3;
        #pragma unroll
        for (int kk = 0; kk < 2; kk++) {
            unsigned af[4][4], b1f[2][4], b3f[2][4];
            #pragma unroll
            for (int mi = 0; mi < 4; mi++) {
                int r = warp_m + mi*16 + (lane & 15);
                int cH = kk*16 + ((lane >> 4) << 3);
                ldm_x4(af[mi][0], af[mi][1], af[mi][2], af[mi][3], sA[b] + (r*LDP + cH)*2);
            }
            #pragma unroll
            for (int pj = 0; pj < 2; pj++) {
                int n = warp_n + pj*16 + (lane & 7) + ((lane >> 4) << 3);
                int cH = kk*16 + (((lane >> 3) & 1) << 3);
                ldm_x4(b1f[pj][0], b1f[pj][1], b1f[pj][2], b1f[pj][3], sB1[b] + (n*LDP + cH)*2);
                ldm_x4(b3f[pj][0], b3f[pj][1], b3f[pj][2], b3f[pj][3], sB3[b] + (n*LDP + cH)*2);
            }
            #pragma unroll
            for (int mi = 0; mi < 4; mi++)
                #pragma unroll
                for (int nj = 0; nj < 4; nj++) {
                    mma16816(a1[mi][nj][0], a1[mi][nj][1], a1[mi][nj][2], a1[mi][nj][3],
                             af[mi][0], af[mi][1], af[mi][2], af[mi][3],
                             b1f[nj >> 1][(nj & 1)*2], b1f[nj >> 1][(nj & 1)*2 + 1]);
                    mma16816(a3[mi][nj][0], a3[mi][nj][1], a3[mi][nj][2], a3[mi][nj][3],
                             af[mi][0], af[mi][1], af[mi][2], af[mi][3],
                             b3f[nj >> 1][(nj & 1)*2], b3f[nj >> 1][(nj & 1)*2 + 1]);
                }
        }
    }

    int lrow = lane >> 2;
    int lcol = (lane & 3) * 2;
    #pragma unroll
    for (int mi = 0; mi < 4; mi++) {
        #pragma unroll
        for (int half = 0; half < 2; half++) {
            int grow = row0 + warp_m + mi*16 + lrow + half*8;
            long obase = (long)grow*HDIM + tileN*GBN + warp_n;
            #pragma unroll
            for (int nj = 0; nj < 4; nj++) {
                float u0 = a1[mi][nj][half*2 + 0];
                float u1 = a1[mi][nj][half*2 + 1];
                float w0 = a3[mi][nj][half*2 + 0];
                float w1 = a3[mi][nj][half*2 + 1];
                float g0 = u0 / (1.f + __expf(-u0)) * w0;
                float g1 = u1 / (1.f + __expf(-u1)) * w1;
                *(__half2*)(G + obase + nj*8 + lcol) = __floats2half2_rn(g0, g1);
            }
        }
    }
}

// ---------------- FlashAttention-2 HMMA causal attention: 3-deep KV ring, 1 barrier/tile ----------------
#define ASTR 72
#define QKVS (3*CC)
#define FQT 128
#define DSM_F ((FQT*ASTR + 6*64*ASTR)*2)
__global__ __launch_bounds__(256)
void fattn_k(const __half* __restrict__ qkv, __half* __restrict__ y) {
    extern __shared__ __half fsm[];
    int qb = (int)gridDim.x - 1 - (int)blockIdx.x;
    int h = blockIdx.y, b = blockIdx.z;
    int tid = threadIdx.x, wid = tid >> 5, lane = tid & 31;

    unsigned uQ = s2u(fsm);
    unsigned uK[3] = { s2u(fsm + FQT*ASTR),
                       s2u(fsm + FQT*ASTR + 64*ASTR),
                       s2u(fsm + FQT*ASTR + 2*64*ASTR) };
    unsigned uV[3] = { s2u(fsm + FQT*ASTR + 3*64*ASTR),
                       s2u(fsm + FQT*ASTR + 4*64*ASTR),
                       s2u(fsm + FQT*ASTR + 5*64*ASTR) };

    long qbase = (long)(b*TT + qb*FQT)*QKVS + h*DD;
    #pragma unroll
    for (int c = 0; c < 4; c++) {
        int id = tid + c*256;
        int r = id >> 3, ch = id & 7;
        CPA16(uQ + (r*ASTR + ch*8)*2, qkv + qbase + (long)r*QKVS + ch*8);
    }
    asm volatile("cp.async.commit_group;");

    auto load_kv = [&](int s) {
        int bb = s % 3;
        long kvb = (long)(b*TT + s*64)*QKVS + h*DD + CC;
        #pragma unroll
        for (int c = 0; c < 2; c++) {
            int id = tid + c*256;
            int r = id >> 3, ch = id & 7;
            CPA16(uK[bb] + (r*ASTR + ch*8)*2, qkv + kvb + (long)r*QKVS + ch*8);
            CPA16(uV[bb] + (r*ASTR + ch*8)*2, qkv + kvb + CC + (long)r*QKVS + ch*8);
        }
        asm volatile("cp.async.commit_group;");
    };

    int nkt = 2*qb + 2;
    load_kv(0);
    if (nkt > 1) load_kv(1);

    bool qloaded = false;
    float m0 = -1e30f, m1 = -1e30f, l0 = 0.f, l1 = 0.f;
    float oa[8][4] = {};
    unsigned qa[4][4];

    for (int kt = 0; kt < nkt; kt++) {
        if (kt + 1 < nkt) asm volatile("cp.async.wait_group 1;");
        else              asm volatile("cp.async.wait_group 0;");
        __syncthreads();
        if (kt + 2 < nkt) load_kv(kt + 2);
        if (!qloaded) {
            #pragma unroll
            for (int kk = 0; kk < 4; kk++) {
                int r = wid*16 + (lane & 15);
                int cH = kk*16 + ((lane >> 4) << 3);
                ldm_x4(qa[kk][0], qa[kk][1], qa[kk][2], qa[kk][3], uQ + (r*ASTR + cH)*2);
            }
            qloaded = true;
        }
        int bb = kt % 3;

        float sc[8][4] = {};
        #pragma unroll
        for (int kk = 0; kk < 4; kk++) {
            unsigned bf[4][4];
            #pragma unroll
            for (int pj = 0; pj < 4; pj++) {
                int n = pj*16 + (lane & 7) + ((lane >> 4) << 3);
                int cH = kk*16 + (((lane >> 3) & 1) << 3);
                ldm_x4(bf[pj][0], bf[pj][1], bf[pj][2], bf[pj][3], uK[bb] + (n*ASTR + cH)*2);
            }
            #pragma unroll
            for (int nj = 0; nj < 8; nj++)
                mma16816(sc[nj][0], sc[nj][1], sc[nj][2], sc[nj][3],
                         qa[kk][0], qa[kk][1], qa[kk][2], qa[kk][3],
                         bf[nj >> 1][(nj & 1)*2], bf[nj >> 1][(nj & 1)*2 + 1]);
        }

        if (kt >= 2*qb) {
            int rg = qb*FQT + wid*16 + (lane >> 2);
            #pragma unroll
            for (int nj = 0; nj < 8; nj++) {
                int cg = kt*64 + nj*8 + (lane & 3)*2;
                if (cg     > rg)   sc[nj][0] = -1e30f;
                if (cg + 1 > rg)   sc[nj][1] = -1e30f;
                if (cg     > rg+8) sc[nj][2] = -1e30f;
                if (cg + 1 > rg+8) sc[nj][3] = -1e30f;
            }
        }

        float rm0 = -1e30f, rm1 = -1e30f;
        #pragma unroll
        for (int nj = 0; nj < 8; nj++) {
            rm0 = fmaxf(rm0, fmaxf(sc[nj][0], sc[nj][1]));
            rm1 = fmaxf(rm1, fmaxf(sc[nj][2], sc[nj][3]));
        }
        rm0 = fmaxf(rm0, __shfl_xor_sync(0xffffffffu, rm0, 1));
        rm0 = fmaxf(rm0, __shfl_xor_sync(0xffffffffu, rm0, 2));
        rm1 = fmaxf(rm1, __shfl_xor_sync(0xffffffffu, rm1, 1));
        rm1 = fmaxf(rm1, __shfl_xor_sync(0xffffffffu, rm1, 2));
        float mn0 = fmaxf(m0, rm0), mn1 = fmaxf(m1, rm1);
        float corr0 = exp2f(m0 - mn0), corr1 = exp2f(m1 - mn1);
        m0 = mn0; m1 = mn1;

        unsigned pa[4][4];
        float ps0 = 0.f, ps1 = 0.f;
        #pragma unroll
        for (int j = 0; j < 4; j++) {
            float p00 = exp2f(sc[2*j][0]   - m0), p01 = exp2f(sc[2*j][1]   - m0);
            float p02 = exp2f(sc[2*j][2]   - m1), p03 = exp2f(sc[2*j][3]   - m1);
            float p10 = exp2f(sc[2*j+1][0] - m0), p11 = exp2f(sc[2*j+1][1] - m0);
            float p12 = exp2f(sc[2*j+1][2] - m1), p13 = exp2f(sc[2*j+1][3] - m1);
            ps0 += p00 + p01 + p10 + p11;
            ps1 += p02 + p03 + p12 + p13;
            __half2 h0 = __floats2half2_rn(p00, p01);
            __half2 h1 = __floats2half2_rn(p02, p03);
            __half2 h2 = __floats2half2_rn(p10, p11);
            __half2 h3 = __floats2half2_rn(p12, p13);
            pa[j][0] = *(unsigned*)&h0;
            pa[j][1] = *(unsigned*)&h1;
            pa[j][2] = *(unsigned*)&h2;
            pa[j][3] = *(unsigned*)&h3;
        }
        ps0 += __shfl_xor_sync(0xffffffffu, ps0, 1);
        ps0 += __shfl_xor_sync(0xffffffffu, ps0, 2);
        ps1 += __shfl_xor_sync(0xffffffffu, ps1, 1);
        ps1 += __shfl_xor_sync(0xffffffffu, ps1, 2);
        l0 = l0*corr0 + ps0;
        l1 = l1*corr1 + ps1;

        #pragma unroll
        for (int nj = 0; nj < 8; nj++) {
            oa[nj][0] *= corr0; oa[nj][1] *= corr0;
            oa[nj][2] *= corr1; oa[nj][3] *= corr1;
        }

        #pragma unroll
        for (int j = 0; j < 4; j++) {
            unsigned vf[4][4];
            #pragma unroll
            for (int pd = 0; pd < 4; pd++) {
                int r = j*16 + (lane & 15);
                int cH = pd*16 + ((lane >> 4) << 3);
                ldm_x4t(vf[pd][0], vf[pd][1], vf[pd][2], vf[pd][3], uV[bb] + (r*ASTR + cH)*2);
            }
            #pragma unroll
            for (int dn = 0; dn < 8; dn++)
                mma16816(oa[dn][0], oa[dn][1], oa[dn][2], oa[dn][3],
                         pa[j][0], pa[j][1], pa[j][2], pa[j][3],
                         vf[dn >> 1][(dn & 1)*2], vf[dn >> 1][(dn & 1)*2 + 1]);
        }
    }

    float il0 = 1.f/l0, il1 = 1.f/l1;
    int r0 = qb*FQT + wid*16 + (lane >> 2);
    #pragma unroll
    for (int dn = 0; dn < 8; dn++) {
        int col = dn*8 + (lane & 3)*2;
        long o0 = ((long)(b*TT + r0)*HH + h)*DD + col;
        long o1 = ((long)(b*TT + r0 + 8)*HH + h)*DD + col;
        *(__half2*)(y + o0) = __floats2half2_rn(oa[dn][0]*il0, oa[dn][1]*il0);
        *(__half2*)(y + o1) = __floats2half2_rn(oa[dn][2]*il1, oa[dn][3]*il1);
    }
}

// ---------------- scatter with fused offset computation ----------------
__global__ void scatter_k(const int* __restrict__ idx2, const float* __restrict__ wts2,
                          int* __restrict__ cursor, const int* __restrict__ counts,
                          int* __restrict__ perm, float* __restrict__ gatew,
                          int* __restrict__ poff) {
    __shared__ int spoff[EE+1];
    if (threadIdx.x == 0) {
        int o = 0;
        #pragma unroll
        for (int e = 0; e < EE; e++) {
            spoff[e] = o;
            o += ((counts[e] + 127)/128)*128;
        }
        spoff[EE] = o;
        if (blockIdx.x == 0) {
            #pragma unroll
            for (int e = 0; e <= EE; e++) poff[e] = spoff[e];
        }
    }
    __syncthreads();
    int t = blockIdx.x*blockDim.x + threadIdx.x;
    if (t >= M0) return;
    for (int kk = 0; kk < 2; kk++) {
        int e = idx2[t*2 + kk];
        int pos = atomicAdd(&cursor[e], 1);
        int r = spoff[e] + pos;
        perm[r] = t; gatew[r] = wts2[t*2 + kk];
    }
}

// ---------------- launch ----------------
static void* sym(const void* s) { void* p = nullptr; cudaGetSymbolAddress(&p, s); return p; }

extern "C" void kernel_launch(void* const* d_in, const int* in_sizes, int n_in,
                              void* d_out, int out_size) {
    const float* x    = (const float*)d_in[0];
    const float* rc   = (const float*)d_in[1];
    const float* rs   = (const float*)d_in[2];
    const float* anw  = (const float*)d_in[3];
    const float* qw   = (const float*)d_in[4];
    const float* kw   = (const float*)d_in[5];
    const float* vw   = (const float*)d_in[6];
    const float* ow   = (const float*)d_in[7];
    const float* fnw  = (const float*)d_in[8];
    const float* rw   = (const float*)d_in[9];
    const float* w1   = (const float*)d_in[10];
    const float* w2   = (const float*)d_in[11];
    const float* w3   = (const float*)d_in[12];
    float* out = (float*)d_out;

    __half* h16   = (__half*)sym(g_h16);
    __half* qkv16 = (__half*)sym(g_qkv16);
    __half* y16   = (__half*)sym(g_y16);
    __half* hn16  = (__half*)sym(g_hn16);
    __half* gb16  = (__half*)sym(g_gb16);
    __half* w16   = (__half*)sym(g_w16all);
    __half* wqkv16= w16;
    __half* ow16  = w16 + OFF_OW;
    __half* w116  = w16 + OFF_W1;
    __half* w216  = w16 + OFF_W2;
    __half* w316  = w16 + OFF_W3;
    int*   counts = (int*)sym(g_counts);
    int*   cursor = (int*)sym(g_cursor);
    int*   poff   = (int*)sym(g_poff);
    int*   perm   = (int*)sym(g_perm);
    float* gatew  = (float*)sym(g_gatew);
    int*   idx2   = (int*)sym(g_idx2);
    float* wts2   = (float*)sym(g_wts2);

    cudaFuncSetAttribute(gemm16_k, cudaFuncAttributeMaxDynamicSharedMemorySize, DSM_G);
    cudaFuncSetAttribute(moe13_k, cudaFuncAttributeMaxDynamicSharedMemorySize, DSM_M);
    cudaFuncSetAttribute(fattn_k, cudaFuncAttributeMaxDynamicSharedMemorySize, DSM_F);

    // 0) fused: weight conversion + MoE init + attn rmsnorm (partitioned grid, overlapped)
    convw_rms_k<<<CONVB + M0, 256>>>((const float4*)qw, (const float4*)kw, (const float4*)vw,
                                     (const float4*)ow, (const float4*)w1, (const float4*)w2,
                                     (const float4*)w3, (__half2*)w16, counts, cursor, perm, gatew,
                                     x, anw, h16);
    // 1) fused QKV projection with rope epilogue (fp16 out, q in log2 domain)
    gemm16_k<<<dim3(3*CC/GBN, M0/GBM), 128, DSM_G>>>(h16, wqkv16, nullptr, qkv16, 3*CC, CC,
                                                     nullptr, nullptr, nullptr, nullptr, 0, nullptr, rc, rs);
    // 2) causal flash attention (3-deep KV ring)
    fattn_k<<<dim3(TT/FQT, HH, BB), 256, DSM_F>>>(qkv16, y16);
    // 3) output projection + residual -> out   <- ncu capture slot
    gemm16_k<<<dim3(CC/GBN, M0/GBM), 128, DSM_G>>>(y16, ow16, out, nullptr, CC, CC,
                                                   x, nullptr, nullptr, nullptr, 0, nullptr, nullptr, nullptr);
    // 4) fused ffn rmsnorm + router
    rmsnorm_router_k<<<M0, 256>>>(out, fnw, hn16, rw, idx2, wts2, counts);
    // 5) scatter with fused offsets
    scatter_k<<<(M0 + 255)/256, 256>>>(idx2, wts2, cursor, counts, perm, gatew, poff);
    // 6) fused expert up-projection + silu*mul
    moe13_k<<<dim3(HDIM/GBN, MG/GBM), 256, DSM_M>>>(hn16, w116, w316, gb16, perm, poff);
    //    down-projection: gate-scaled atomic scatter into out
    gemm16_k<<<dim3(CC/GBN, MG/GBM), 128, DSM_G>>>(gb16, w216, out, nullptr, CC, HDIM,
                                                   nullptr, nullptr, poff, gatew, (long)CC*HDIM, perm, nullptr, nullptr);
}